// round 6
// baseline (speedup 1.0000x reference)
#include <cuda_runtime.h>
#include <cuda_bf16.h>

// Problem constants (fixed by the dataset)
#define NMAX 50000
#define EMAX 800000
#define GMAXG 64

// ---------------- scratch (device globals; no allocation allowed) -------------
__device__ unsigned int g_mbits[2 * NMAX];     // result mask bits (64 bits/node)
__device__ unsigned int g_nodebits[2 * NMAX];  // per-node mask[n,f]>0 bits
__device__ int g_cnt[NMAX];
__device__ int g_off[NMAX + 1];
__device__ int g_cursor[NMAX];
__device__ int g_csr[EMAX];                    // src ids grouped by dst
__device__ __align__(16) float g_xw[(size_t)NMAX * 256];
__device__ __align__(16) float g_gat[(size_t)NMAX * 256];
__device__ __align__(16) float g_as[NMAX * 4];
__device__ __align__(16) float g_ad[NMAX * 4];
__device__ int g_deg[GMAXG];

__device__ __forceinline__ float lrelu(float a) { return fmaxf(a, 0.2f * a); }

// ---------------- init: zero accumulators ------------------------------------
__global__ void k_init(int n) {
    int i = blockIdx.x * blockDim.x + threadIdx.x;
    if (i < 2 * n) g_mbits[i] = 0u;
    if (i < n) g_cnt[i] = 0;
    if (i < GMAXG) g_deg[i] = 0;
}

// ---------------- per-node mask bits: bit f = (mask[n,f] > 0) ----------------
__global__ void k_nodebits(const float* __restrict__ mask, int n) {
    int gw = (blockIdx.x * blockDim.x + threadIdx.x) >> 5;
    int lane = threadIdx.x & 31;
    int node = gw >> 1, half = gw & 1;
    if (node >= n) return;
    float v = mask[node * 64 + half * 32 + lane];
    unsigned int b = __ballot_sync(0xffffffffu, v > 0.f);
    if (lane == 0) g_nodebits[node * 2 + half] = b;
}

// ---------------- per-edge: mask OR-scatter + in-degree count ----------------
// edge_index is int32 (harness canonicalizes int64 -> int32)
__global__ void k_edge1(const int* __restrict__ ei, int E, int n) {
    int e = blockIdx.x * blockDim.x + threadIdx.x;
    if (e >= E) return;
    int r = ei[e];       // edge_index[0] = row (mask target) = GAT src
    int c = ei[E + e];   // edge_index[1] = col (mask source) = GAT dst
    if ((unsigned)r >= (unsigned)n || (unsigned)c >= (unsigned)n) return;
    unsigned int b0 = g_nodebits[c * 2];
    unsigned int b1 = g_nodebits[c * 2 + 1];
    atomicOr(&g_mbits[r * 2], b0);
    atomicOr(&g_mbits[r * 2 + 1], b1);
    atomicAdd(&g_cnt[c], 1);
}

// ---------------- graph-size histogram (batch_idx -> deg) --------------------
__global__ void k_deg(const int* __restrict__ batch, int n) {
    __shared__ int h[GMAXG];
    if (threadIdx.x < GMAXG) h[threadIdx.x] = 0;
    __syncthreads();
    for (int i = blockIdx.x * blockDim.x + threadIdx.x; i < n;
         i += gridDim.x * blockDim.x) {
        int b = batch[i];
        if (b >= 0 && b < GMAXG) atomicAdd(&h[b], 1);
    }
    __syncthreads();
    if (threadIdx.x < GMAXG) atomicAdd(&g_deg[threadIdx.x], h[threadIdx.x]);
}

// ---------------- exclusive scan of cnt -> off, cursor (single block) --------
__global__ void k_scan(int n) {
    __shared__ int sums[1024];
    int tid = threadIdx.x;
    int per = (n + 1023) >> 10;
    int start = tid * per;
    int stop = min(start + per, n);
    int s = 0;
    for (int i = start; i < stop; i++) s += g_cnt[i];
    sums[tid] = s;
    __syncthreads();
    for (int d = 1; d < 1024; d <<= 1) {
        int v = (tid >= d) ? sums[tid - d] : 0;
        __syncthreads();
        sums[tid] += v;
        __syncthreads();
    }
    if (tid == 0) g_off[n] = sums[1023];
    int run = (tid > 0) ? sums[tid - 1] : 0;
    for (int i = start; i < stop; i++) {
        g_off[i] = run;
        g_cursor[i] = run;
        run += g_cnt[i];
    }
}

// ---------------- CSR fill: group src ids by dst -----------------------------
__global__ void k_fill(const int* __restrict__ ei, int E, int n) {
    int e = blockIdx.x * blockDim.x + threadIdx.x;
    if (e >= E) return;
    int s = ei[e];
    int d = ei[E + e];
    if ((unsigned)s >= (unsigned)n || (unsigned)d >= (unsigned)n) return;
    int pos = atomicAdd(&g_cursor[d], 1);
    g_csr[pos] = s;
}

// ---------------- xw = x @ W_gat^T  (+ per-head attention scalars) -----------
// 256 threads, 16 rows per block. Thread t owns output channel t for 16 rows.
__global__ void k_gemm(const float* __restrict__ x, const float* __restrict__ Wg,
                       const float* __restrict__ attS, const float* __restrict__ attD,
                       int n) {
    __shared__ float xs[16 * 68];
    __shared__ float partS[16][8];
    __shared__ float partD[16][8];
    int tid = threadIdx.x;
    int row0 = blockIdx.x * 16;

    for (int idx = tid; idx < 16 * 64; idx += 256) {
        int r = idx >> 6, f = idx & 63;
        int row = row0 + r;
        xs[r * 68 + f] = (row < n) ? x[row * 64 + f] : 0.f;
    }
    __syncthreads();

    float acc[16];
#pragma unroll
    for (int r = 0; r < 16; r++) acc[r] = 0.f;

    const float4* wrow = (const float4*)(Wg + tid * 64);
#pragma unroll
    for (int fc = 0; fc < 16; fc++) {
        float4 w = wrow[fc];
#pragma unroll
        for (int r = 0; r < 16; r++) {
            float4 xv = *(const float4*)(xs + r * 68 + fc * 4);
            acc[r] = fmaf(w.x, xv.x,
                      fmaf(w.y, xv.y, fmaf(w.z, xv.z, fmaf(w.w, xv.w, acc[r]))));
        }
    }

#pragma unroll
    for (int r = 0; r < 16; r++) {
        int row = row0 + r;
        if (row < n) g_xw[(size_t)row * 256 + tid] = acc[r];
    }

    // a_s[n,h] = sum_d xw[n,h,d] * att_src[h,d]  (channel index == h*64+d == tid)
    float aS = attS[tid], aD = attD[tid];
    int wid = tid >> 5, lane = tid & 31;
#pragma unroll
    for (int r = 0; r < 16; r++) {
        float sS = acc[r] * aS, sD = acc[r] * aD;
#pragma unroll
        for (int o = 16; o; o >>= 1) {
            sS += __shfl_xor_sync(0xffffffffu, sS, o);
            sD += __shfl_xor_sync(0xffffffffu, sD, o);
        }
        if (lane == 0) { partS[r][wid] = sS; partD[r][wid] = sD; }
    }
    __syncthreads();
    if (tid < 128) {
        int r = tid >> 3, h = (tid >> 1) & 3, sd = tid & 1;
        int row = row0 + r;
        if (row < n) {
            if (sd == 0) g_as[row * 4 + h] = partS[r][2 * h] + partS[r][2 * h + 1];
            else         g_ad[row * 4 + h] = partD[r][2 * h] + partD[r][2 * h + 1];
        }
    }
}

// ---------------- attention: warp per destination node -----------------------
// pass1: segment max over incoming edges + self loop
// pass2: exp, denom accumulate, weighted gather of xw[src]
__global__ void k_attn(int n) {
    __shared__ int ssrc[8][32];
    __shared__ float4 sp[8][32];
    int w = threadIdx.x >> 5, lane = threadIdx.x & 31;
    int i = blockIdx.x * 8 + w;
    if (i >= n) return;

    int off0 = g_off[i];
    int len = g_off[i + 1] - off0;

    const float4* as4 = (const float4*)g_as;
    float4 ad = ((const float4*)g_ad)[i];
    float4 asl = as4[i];

    float es0 = lrelu(asl.x + ad.x);
    float es1 = lrelu(asl.y + ad.y);
    float es2 = lrelu(asl.z + ad.z);
    float es3 = lrelu(asl.w + ad.w);
    float mx0 = es0, mx1 = es1, mx2 = es2, mx3 = es3;

    for (int k = lane; k < len; k += 32) {
        int s = g_csr[off0 + k];
        float4 a = as4[s];
        mx0 = fmaxf(mx0, lrelu(a.x + ad.x));
        mx1 = fmaxf(mx1, lrelu(a.y + ad.y));
        mx2 = fmaxf(mx2, lrelu(a.z + ad.z));
        mx3 = fmaxf(mx3, lrelu(a.w + ad.w));
    }
#pragma unroll
    for (int o = 16; o; o >>= 1) {
        mx0 = fmaxf(mx0, __shfl_xor_sync(0xffffffffu, mx0, o));
        mx1 = fmaxf(mx1, __shfl_xor_sync(0xffffffffu, mx1, o));
        mx2 = fmaxf(mx2, __shfl_xor_sync(0xffffffffu, mx2, o));
        mx3 = fmaxf(mx3, __shfl_xor_sync(0xffffffffu, mx3, o));
    }

    // self-loop exp terms (same value in all lanes; numerator use is per-channel)
    float self0 = __expf(es0 - mx0);
    float self1 = __expf(es1 - mx1);
    float self2 = __expf(es2 - mx2);
    float self3 = __expf(es3 - mx3);
    // denominator is warp-sum-reduced at the end: seed self term on ONE lane only
    float den0 = (lane == 0) ? self0 : 0.f;
    float den1 = (lane == 0) ? self1 : 0.f;
    float den2 = (lane == 0) ? self2 : 0.f;
    float den3 = (lane == 0) ? self3 : 0.f;

    const float2* xw2 = (const float2*)g_xw;
    const float2* xi = xw2 + (size_t)i * 128 + lane;
    float2 acc0, acc1, acc2, acc3;
    { float2 v = xi[0];  acc0 = make_float2(self0 * v.x, self0 * v.y); }
    { float2 v = xi[32]; acc1 = make_float2(self1 * v.x, self1 * v.y); }
    { float2 v = xi[64]; acc2 = make_float2(self2 * v.x, self2 * v.y); }
    { float2 v = xi[96]; acc3 = make_float2(self3 * v.x, self3 * v.y); }

    for (int base = 0; base < len; base += 32) {
        int k = base + lane;
        if (k < len) {
            int s = g_csr[off0 + k];
            float4 a = as4[s];
            float p0 = __expf(lrelu(a.x + ad.x) - mx0);
            float p1 = __expf(lrelu(a.y + ad.y) - mx1);
            float p2 = __expf(lrelu(a.z + ad.z) - mx2);
            float p3 = __expf(lrelu(a.w + ad.w) - mx3);
            den0 += p0; den1 += p1; den2 += p2; den3 += p3;
            ssrc[w][lane] = s;
            sp[w][lane] = make_float4(p0, p1, p2, p3);
        }
        __syncwarp();
        int cnt = min(32, len - base);
#pragma unroll 2
        for (int t = 0; t < cnt; t++) {
            int s = ssrc[w][t];
            float4 p = sp[w][t];
            const float2* xs2 = xw2 + (size_t)s * 128 + lane;
            float2 v0 = xs2[0], v1 = xs2[32], v2 = xs2[64], v3 = xs2[96];
            acc0.x = fmaf(p.x, v0.x, acc0.x); acc0.y = fmaf(p.x, v0.y, acc0.y);
            acc1.x = fmaf(p.y, v1.x, acc1.x); acc1.y = fmaf(p.y, v1.y, acc1.y);
            acc2.x = fmaf(p.z, v2.x, acc2.x); acc2.y = fmaf(p.z, v2.y, acc2.y);
            acc3.x = fmaf(p.w, v3.x, acc3.x); acc3.y = fmaf(p.w, v3.y, acc3.y);
        }
        __syncwarp();
    }

#pragma unroll
    for (int o = 16; o; o >>= 1) {
        den0 += __shfl_xor_sync(0xffffffffu, den0, o);
        den1 += __shfl_xor_sync(0xffffffffu, den1, o);
        den2 += __shfl_xor_sync(0xffffffffu, den2, o);
        den3 += __shfl_xor_sync(0xffffffffu, den3, o);
    }
    float inv0 = 1.f / (den0 + 1e-16f);
    float inv1 = 1.f / (den1 + 1e-16f);
    float inv2 = 1.f / (den2 + 1e-16f);
    float inv3 = 1.f / (den3 + 1e-16f);

    float2* go = (float2*)g_gat + (size_t)i * 128 + lane;
    go[0]  = make_float2(acc0.x * inv0, acc0.y * inv0);
    go[32] = make_float2(acc1.x * inv1, acc1.y * inv1);
    go[64] = make_float2(acc2.x * inv2, acc2.y * inv2);
    go[96] = make_float2(acc3.x * inv3, acc3.y * inv3);
}

// ---------------- final: out = ((gat+bias)*mask) @ W_lin^T + b_lin, norm -----
// 256 threads, 32 rows per block; thread t: d2 = t&63, rows rg*8..rg*8+7.
__global__ void k_final(const float* __restrict__ Wl, const float* __restrict__ bg,
                        const float* __restrict__ bl,
                        const int* __restrict__ batch,
                        float* __restrict__ out, int n) {
    __shared__ float grow[32 * 260];
    int tid = threadIdx.x;
    int row0 = blockIdx.x * 32;

    for (int idx = tid; idx < 32 * 256; idx += 256) {
        int r = idx >> 8, c = idx & 255;
        int row = row0 + r;
        float v = 0.f;
        if (row < n) {
            unsigned int mb = g_mbits[row * 2 + ((c >> 5) & 1)];
            float bit = (float)((mb >> (c & 31)) & 1u);
            v = (g_gat[(size_t)row * 256 + c] + bg[c]) * bit;
        }
        grow[r * 260 + c] = v;
    }
    __syncthreads();

    int d2 = tid & 63, rg = tid >> 6;
    float acc[8];
#pragma unroll
    for (int k = 0; k < 8; k++) acc[k] = 0.f;

    const float4* wl4 = (const float4*)(Wl + d2 * 256);
#pragma unroll 4
    for (int c4 = 0; c4 < 64; c4++) {
        float4 wv = wl4[c4];
#pragma unroll
        for (int k = 0; k < 8; k++) {
            float4 g = *(const float4*)(grow + (rg * 8 + k) * 260 + c4 * 4);
            acc[k] = fmaf(wv.x, g.x,
                      fmaf(wv.y, g.y, fmaf(wv.z, g.z, fmaf(wv.w, g.w, acc[k]))));
        }
    }

    float b = bl[d2];
#pragma unroll
    for (int k = 0; k < 8; k++) {
        int row = row0 + rg * 8 + k;
        if (row < n) {
            int bi = batch[row];
            int dd = (bi >= 0 && bi < GMAXG) ? g_deg[bi] : 0;
            float dv = (dd > 0) ? (float)dd : 1.f;
            out[row * 64 + d2] = (acc[k] + b) * rsqrtf(dv);
        }
    }
}

// ---------------- launcher ----------------------------------------------------
extern "C" void kernel_launch(void* const* d_in, const int* in_sizes, int n_in,
                              void* d_out, int out_size) {
    const float* x     = (const float*)d_in[0];
    const float* mask  = (const float*)d_in[1];
    const int*   ei    = (const int*)d_in[2];
    const int*   batch = (const int*)d_in[3];
    const float* Wg    = (const float*)d_in[4];
    const float* attS  = (const float*)d_in[5];
    const float* attD  = (const float*)d_in[6];
    const float* bg    = (const float*)d_in[7];
    const float* Wl    = (const float*)d_in[8];
    const float* bl    = (const float*)d_in[9];
    float* out = (float*)d_out;

    int n = in_sizes[0] / 64;
    int E = in_sizes[2] / 2;

    k_init    <<<(2 * n + 255) / 256, 256>>>(n);
    k_nodebits<<<(64 * n + 255) / 256, 256>>>(mask, n);
    k_edge1   <<<(E + 255) / 256, 256>>>(ei, E, n);
    k_deg     <<<128, 256>>>(batch, n);
    k_scan    <<<1, 1024>>>(n);
    k_fill    <<<(E + 255) / 256, 256>>>(ei, E, n);
    k_gemm    <<<(n + 15) / 16, 256>>>(x, Wg, attS, attD, n);
    k_attn    <<<(n + 7) / 8, 256>>>(n);
    k_final   <<<(n + 31) / 32, 256>>>(Wl, bg, bl, batch, out, n);
}

// round 9
// speedup vs baseline: 1.0425x; 1.0425x over previous
#include <cuda_runtime.h>
#include <cuda_bf16.h>

// Problem constants (fixed by the dataset)
#define NMAX 50000
#define EMAX 800000
#define GMAXG 64

// ---------------- scratch (device globals; no allocation allowed) -------------
__device__ __align__(8) unsigned int g_mbits[2 * NMAX];     // result mask bits
__device__ __align__(8) unsigned int g_nodebits[2 * NMAX];  // mask[n,f]>0 bits
__device__ int g_cnt[NMAX];
__device__ int g_off[NMAX + 1];
__device__ int g_cursor[NMAX];
__device__ int g_csr[EMAX];                    // src ids grouped by dst
__device__ __align__(16) float g_xw[(size_t)NMAX * 256];
__device__ __align__(16) float g_gat[(size_t)NMAX * 256];
__device__ __align__(16) float g_as[NMAX * 4];
__device__ __align__(16) float g_ad[NMAX * 4];
__device__ int g_deg[GMAXG];

__device__ __forceinline__ float lrelu(float a) { return fmaxf(a, 0.2f * a); }

// ---------------- nodebits + zero all accumulators ---------------------------
// one warp per (node, half): bit f = (mask[n, half*32+f] > 0); also zeroes
// g_mbits / g_cnt / g_deg so no separate init kernel is needed.
__global__ void k_nodebits(const float* __restrict__ mask, int n) {
    int t = blockIdx.x * blockDim.x + threadIdx.x;
    if (t < n) g_cnt[t] = 0;
    if (t < GMAXG) g_deg[t] = 0;
    int gw = t >> 5;
    int lane = threadIdx.x & 31;
    int node = gw >> 1, half = gw & 1;
    if (node >= n) return;
    float v = mask[node * 64 + half * 32 + lane];
    unsigned int b = __ballot_sync(0xffffffffu, v > 0.f);
    if (lane == 0) {
        g_nodebits[node * 2 + half] = b;
        g_mbits[node * 2 + half] = 0u;
    }
}

// ---------------- per-edge: 64-bit mask OR-scatter + in-degree count ---------
__global__ void k_edge1(const int* __restrict__ ei, int E, int n) {
    int e = blockIdx.x * blockDim.x + threadIdx.x;
    if (e >= E) return;
    int r = ei[e];       // edge_index[0] = row (mask target) = GAT src
    int c = ei[E + e];   // edge_index[1] = col (mask source) = GAT dst
    if ((unsigned)r >= (unsigned)n || (unsigned)c >= (unsigned)n) return;
    unsigned long long nb = ((const unsigned long long*)g_nodebits)[c];
    atomicOr((unsigned long long*)g_mbits + r, nb);
    atomicAdd(&g_cnt[c], 1);
}

// ---------------- graph-size histogram (batch_idx -> deg) --------------------
__global__ void k_deg(const int* __restrict__ batch, int n) {
    __shared__ int h[GMAXG];
    if (threadIdx.x < GMAXG) h[threadIdx.x] = 0;
    __syncthreads();
    for (int i = blockIdx.x * blockDim.x + threadIdx.x; i < n;
         i += gridDim.x * blockDim.x) {
        int b = batch[i];
        if (b >= 0 && b < GMAXG) atomicAdd(&h[b], 1);
    }
    __syncthreads();
    if (threadIdx.x < GMAXG) atomicAdd(&g_deg[threadIdx.x], h[threadIdx.x]);
}

// ---------------- exclusive scan of cnt -> off, cursor (single block) --------
__global__ void k_scan(int n) {
    __shared__ int sums[1024];
    int tid = threadIdx.x;
    int per = (n + 1023) >> 10;
    int start = tid * per;
    int stop = min(start + per, n);
    int s = 0;
    for (int i = start; i < stop; i++) s += g_cnt[i];
    sums[tid] = s;
    __syncthreads();
    for (int d = 1; d < 1024; d <<= 1) {
        int v = (tid >= d) ? sums[tid - d] : 0;
        __syncthreads();
        sums[tid] += v;
        __syncthreads();
    }
    if (tid == 0) g_off[n] = sums[1023];
    int run = (tid > 0) ? sums[tid - 1] : 0;
    for (int i = start; i < stop; i++) {
        g_off[i] = run;
        g_cursor[i] = run;
        run += g_cnt[i];
    }
}

// ---------------- CSR fill: group src ids by dst -----------------------------
__global__ void k_fill(const int* __restrict__ ei, int E, int n) {
    int e = blockIdx.x * blockDim.x + threadIdx.x;
    if (e >= E) return;
    int s = ei[e];
    int d = ei[E + e];
    if ((unsigned)s >= (unsigned)n || (unsigned)d >= (unsigned)n) return;
    int pos = atomicAdd(&g_cursor[d], 1);
    g_csr[pos] = s;
}

// ---------------- xw = x @ W_gat^T  (+ per-head attention scalars) -----------
// 256 threads, 16 rows per block. Thread t owns output channel t for 16 rows.
__global__ void k_gemm(const float* __restrict__ x, const float* __restrict__ Wg,
                       const float* __restrict__ attS, const float* __restrict__ attD,
                       int n) {
    __shared__ float xs[16 * 68];
    __shared__ float partS[16][8];
    __shared__ float partD[16][8];
    int tid = threadIdx.x;
    int row0 = blockIdx.x * 16;

    for (int idx = tid; idx < 16 * 64; idx += 256) {
        int r = idx >> 6, f = idx & 63;
        int row = row0 + r;
        xs[r * 68 + f] = (row < n) ? x[row * 64 + f] : 0.f;
    }
    __syncthreads();

    float acc[16];
#pragma unroll
    for (int r = 0; r < 16; r++) acc[r] = 0.f;

    const float4* wrow = (const float4*)(Wg + tid * 64);
#pragma unroll
    for (int fc = 0; fc < 16; fc++) {
        float4 w = wrow[fc];
#pragma unroll
        for (int r = 0; r < 16; r++) {
            float4 xv = *(const float4*)(xs + r * 68 + fc * 4);
            acc[r] = fmaf(w.x, xv.x,
                      fmaf(w.y, xv.y, fmaf(w.z, xv.z, fmaf(w.w, xv.w, acc[r]))));
        }
    }

#pragma unroll
    for (int r = 0; r < 16; r++) {
        int row = row0 + r;
        if (row < n) g_xw[(size_t)row * 256 + tid] = acc[r];
    }

    // a_s[n,h] = sum_d xw[n,h,d] * att_src[h,d]  (channel index == h*64+d == tid)
    float aS = attS[tid], aD = attD[tid];
    int wid = tid >> 5, lane = tid & 31;
#pragma unroll
    for (int r = 0; r < 16; r++) {
        float sS = acc[r] * aS, sD = acc[r] * aD;
#pragma unroll
        for (int o = 16; o; o >>= 1) {
            sS += __shfl_xor_sync(0xffffffffu, sS, o);
            sD += __shfl_xor_sync(0xffffffffu, sD, o);
        }
        if (lane == 0) { partS[r][wid] = sS; partD[r][wid] = sD; }
    }
    __syncthreads();
    if (tid < 128) {
        int r = tid >> 3, h = (tid >> 1) & 3, sd = tid & 1;
        int row = row0 + r;
        if (row < n) {
            if (sd == 0) g_as[row * 4 + h] = partS[r][2 * h] + partS[r][2 * h + 1];
            else         g_ad[row * 4 + h] = partD[r][2 * h] + partD[r][2 * h + 1];
        }
    }
}

// ---------------- attention: warp per destination node -----------------------
// Single pass: softmax is shift-invariant and |e| <= ~2 here, so no max pass.
// Each lane holds 8 output channels as two float4 (lo: c=4*lane, hi: c=128+4*lane).
__global__ void k_attn(int n) {
    __shared__ int ssrc[8][32];
    __shared__ float4 sp[8][32];
    int w = threadIdx.x >> 5, lane = threadIdx.x & 31;
    int i = blockIdx.x * 8 + w;
    if (i >= n) return;

    int off0 = g_off[i];
    int len = g_off[i + 1] - off0;

    const float4* as4 = (const float4*)g_as;
    float4 ad = ((const float4*)g_ad)[i];
    float4 asl = as4[i];

    float self0 = __expf(lrelu(asl.x + ad.x));
    float self1 = __expf(lrelu(asl.y + ad.y));
    float self2 = __expf(lrelu(asl.z + ad.z));
    float self3 = __expf(lrelu(asl.w + ad.w));
    // denominator is warp-sum-reduced at the end: seed self term on ONE lane only
    float den0 = (lane == 0) ? self0 : 0.f;
    float den1 = (lane == 0) ? self1 : 0.f;
    float den2 = (lane == 0) ? self2 : 0.f;
    float den3 = (lane == 0) ? self3 : 0.f;

    bool hiHalf = (lane >= 16);          // head = lane/16 within each 128-ch half
    const float4* xw4 = (const float4*)g_xw;
    const float4* xi = xw4 + (size_t)i * 64 + lane;
    float4 accLo, accHi;
    {
        float wl = hiHalf ? self1 : self0;
        float wh = hiHalf ? self3 : self2;
        float4 vl = xi[0], vh = xi[32];
        accLo = make_float4(wl * vl.x, wl * vl.y, wl * vl.z, wl * vl.w);
        accHi = make_float4(wh * vh.x, wh * vh.y, wh * vh.z, wh * vh.w);
    }

    for (int base = 0; base < len; base += 32) {
        int k = base + lane;
        if (k < len) {
            int s = g_csr[off0 + k];
            float4 a = as4[s];
            float p0 = __expf(lrelu(a.x + ad.x));
            float p1 = __expf(lrelu(a.y + ad.y));
            float p2 = __expf(lrelu(a.z + ad.z));
            float p3 = __expf(lrelu(a.w + ad.w));
            den0 += p0; den1 += p1; den2 += p2; den3 += p3;
            ssrc[w][lane] = s;
            sp[w][lane] = make_float4(p0, p1, p2, p3);
        }
        __syncwarp();
        int cnt = min(32, len - base);
#pragma unroll 4
        for (int t = 0; t < cnt; t++) {
            int s = ssrc[w][t];
            float4 p = sp[w][t];
            const float4* xs4 = xw4 + (size_t)s * 64 + lane;
            float4 vl = xs4[0], vh = xs4[32];
            float pl = hiHalf ? p.y : p.x;
            float ph = hiHalf ? p.w : p.z;
            accLo.x = fmaf(pl, vl.x, accLo.x); accLo.y = fmaf(pl, vl.y, accLo.y);
            accLo.z = fmaf(pl, vl.z, accLo.z); accLo.w = fmaf(pl, vl.w, accLo.w);
            accHi.x = fmaf(ph, vh.x, accHi.x); accHi.y = fmaf(ph, vh.y, accHi.y);
            accHi.z = fmaf(ph, vh.z, accHi.z); accHi.w = fmaf(ph, vh.w, accHi.w);
        }
        __syncwarp();
    }

#pragma unroll
    for (int o = 16; o; o >>= 1) {
        den0 += __shfl_xor_sync(0xffffffffu, den0, o);
        den1 += __shfl_xor_sync(0xffffffffu, den1, o);
        den2 += __shfl_xor_sync(0xffffffffu, den2, o);
        den3 += __shfl_xor_sync(0xffffffffu, den3, o);
    }
    float inv0 = 1.f / (den0 + 1e-16f);
    float inv1 = 1.f / (den1 + 1e-16f);
    float inv2 = 1.f / (den2 + 1e-16f);
    float inv3 = 1.f / (den3 + 1e-16f);
    float invLo = hiHalf ? inv1 : inv0;
    float invHi = hiHalf ? inv3 : inv2;

    float4* go = (float4*)g_gat + (size_t)i * 64 + lane;
    go[0]  = make_float4(accLo.x * invLo, accLo.y * invLo,
                         accLo.z * invLo, accLo.w * invLo);
    go[32] = make_float4(accHi.x * invHi, accHi.y * invHi,
                         accHi.z * invHi, accHi.w * invHi);
}

// ---------------- final: out = ((gat+bias)*mask) @ W_lin^T + b_lin, norm -----
// 256 threads, 32 rows per block; thread t: d2 = t&63, rows rg*8..rg*8+7.
__global__ void k_final(const float* __restrict__ Wl, const float* __restrict__ bg,
                        const float* __restrict__ bl,
                        const int* __restrict__ batch,
                        float* __restrict__ out, int n) {
    __shared__ float grow[32 * 260];
    int tid = threadIdx.x;
    int row0 = blockIdx.x * 32;

    for (int idx = tid; idx < 32 * 256; idx += 256) {
        int r = idx >> 8, c = idx & 255;
        int row = row0 + r;
        float v = 0.f;
        if (row < n) {
            unsigned int mb = g_mbits[row * 2 + ((c >> 5) & 1)];
            float bit = (float)((mb >> (c & 31)) & 1u);
            v = (g_gat[(size_t)row * 256 + c] + bg[c]) * bit;
        }
        grow[r * 260 + c] = v;
    }
    __syncthreads();

    int d2 = tid & 63, rg = tid >> 6;
    float acc[8];
#pragma unroll
    for (int k = 0; k < 8; k++) acc[k] = 0.f;

    const float4* wl4 = (const float4*)(Wl + d2 * 256);
#pragma unroll 4
    for (int c4 = 0; c4 < 64; c4++) {
        float4 wv = wl4[c4];
#pragma unroll
        for (int k = 0; k < 8; k++) {
            float4 g = *(const float4*)(grow + (rg * 8 + k) * 260 + c4 * 4);
            acc[k] = fmaf(wv.x, g.x,
                      fmaf(wv.y, g.y, fmaf(wv.z, g.z, fmaf(wv.w, g.w, acc[k]))));
        }
    }

    float b = bl[d2];
#pragma unroll
    for (int k = 0; k < 8; k++) {
        int row = row0 + rg * 8 + k;
        if (row < n) {
            int bi = batch[row];
            int dd = (bi >= 0 && bi < GMAXG) ? g_deg[bi] : 0;
            float dv = (dd > 0) ? (float)dd : 1.f;
            out[row * 64 + d2] = (acc[k] + b) * rsqrtf(dv);
        }
    }
}

// ---------------- launcher ----------------------------------------------------
extern "C" void kernel_launch(void* const* d_in, const int* in_sizes, int n_in,
                              void* d_out, int out_size) {
    const float* x     = (const float*)d_in[0];
    const float* mask  = (const float*)d_in[1];
    const int*   ei    = (const int*)d_in[2];
    const int*   batch = (const int*)d_in[3];
    const float* Wg    = (const float*)d_in[4];
    const float* attS  = (const float*)d_in[5];
    const float* attD  = (const float*)d_in[6];
    const float* bg    = (const float*)d_in[7];
    const float* Wl    = (const float*)d_in[8];
    const float* bl    = (const float*)d_in[9];
    float* out = (float*)d_out;

    int n = in_sizes[0] / 64;
    int E = in_sizes[2] / 2;

    k_nodebits<<<(64 * n + 255) / 256, 256>>>(mask, n);
    k_edge1   <<<(E + 255) / 256, 256>>>(ei, E, n);
    k_deg     <<<128, 256>>>(batch, n);
    k_scan    <<<1, 1024>>>(n);
    k_fill    <<<(E + 255) / 256, 256>>>(ei, E, n);
    k_gemm    <<<(n + 15) / 16, 256>>>(x, Wg, attS, attD, n);
    k_attn    <<<(n + 7) / 8, 256>>>(n);
    k_final   <<<(n + 31) / 32, 256>>>(Wl, bg, bl, batch, out, n);
}

// round 10
// speedup vs baseline: 1.2424x; 1.1917x over previous
#include <cuda_runtime.h>
#include <cuda_bf16.h>

// Problem constants (fixed by the dataset)
#define NMAX 50000
#define EMAX 800000
#define GMAXG 64
#define SCB 1024                 // elements per scan block
#define SCMAXB ((NMAX + SCB - 1) / SCB)

// ---------------- scratch (device globals; no allocation allowed) -------------
__device__ __align__(8) unsigned int g_mbits[2 * NMAX];     // result mask bits
__device__ __align__(8) unsigned int g_nodebits[2 * NMAX];  // mask[n,f]>0 bits
__device__ __align__(16) int g_cnt[NMAX];
__device__ __align__(16) int g_off[NMAX + 4];
__device__ __align__(16) int g_cursor[NMAX];
__device__ int g_bsum[SCMAXB];
__device__ int g_boff[SCMAXB];
__device__ int g_csr[EMAX];                    // src ids grouped by dst
__device__ __align__(16) float g_xw[(size_t)NMAX * 256];
__device__ __align__(16) float g_gat[(size_t)NMAX * 256];
__device__ __align__(16) float g_as[NMAX * 4];
__device__ __align__(16) float g_ad[NMAX * 4];
__device__ int g_deg[GMAXG];

__device__ __forceinline__ float lrelu(float a) { return fmaxf(a, 0.2f * a); }

// ---------------- nodebits + zero all accumulators ---------------------------
__global__ void k_nodebits(const float* __restrict__ mask, int n) {
    int t = blockIdx.x * blockDim.x + threadIdx.x;
    if (t < n) g_cnt[t] = 0;
    if (t < GMAXG) g_deg[t] = 0;
    int gw = t >> 5;
    int lane = threadIdx.x & 31;
    int node = gw >> 1, half = gw & 1;
    if (node >= n) return;
    float v = mask[node * 64 + half * 32 + lane];
    unsigned int b = __ballot_sync(0xffffffffu, v > 0.f);
    if (lane == 0) {
        g_nodebits[node * 2 + half] = b;
        g_mbits[node * 2 + half] = 0u;
    }
}

// ---------------- per-edge: 64-bit mask OR-scatter + in-degree count ---------
__global__ void k_edge1(const int* __restrict__ ei, int E, int n) {
    int e = blockIdx.x * blockDim.x + threadIdx.x;
    if (e >= E) return;
    int r = ei[e];       // edge_index[0] = row (mask target) = GAT src
    int c = ei[E + e];   // edge_index[1] = col (mask source) = GAT dst
    if ((unsigned)r >= (unsigned)n || (unsigned)c >= (unsigned)n) return;
    unsigned long long nb = ((const unsigned long long*)g_nodebits)[c];
    atomicOr((unsigned long long*)g_mbits + r, nb);
    atomicAdd(&g_cnt[c], 1);
}

// ---------------- graph-size histogram (batch_idx -> deg) --------------------
__global__ void k_deg(const int* __restrict__ batch, int n) {
    __shared__ int h[GMAXG];
    if (threadIdx.x < GMAXG) h[threadIdx.x] = 0;
    __syncthreads();
    for (int i = blockIdx.x * blockDim.x + threadIdx.x; i < n;
         i += gridDim.x * blockDim.x) {
        int b = batch[i];
        if (b >= 0 && b < GMAXG) atomicAdd(&h[b], 1);
    }
    __syncthreads();
    if (threadIdx.x < GMAXG) atomicAdd(&g_deg[threadIdx.x], h[threadIdx.x]);
}

// ---------------- multi-block exclusive scan of g_cnt -> g_off/g_cursor ------
// Phase A: per-block (1024 elems, 256 thr, 4/thr) coalesced sum -> g_bsum.
__device__ __forceinline__ void scan_load4(int base, int n,
                                           int& v0, int& v1, int& v2, int& v3) {
    v0 = v1 = v2 = v3 = 0;
    if (base + 3 < n) {
        int4 c = *(const int4*)(g_cnt + base);
        v0 = c.x; v1 = c.y; v2 = c.z; v3 = c.w;
    } else {
        if (base + 0 < n) v0 = g_cnt[base + 0];
        if (base + 1 < n) v1 = g_cnt[base + 1];
        if (base + 2 < n) v2 = g_cnt[base + 2];
        if (base + 3 < n) v3 = g_cnt[base + 3];
    }
}

__global__ void k_scanA(int n) {
    __shared__ int ts[256];
    int tid = threadIdx.x;
    int base = blockIdx.x * SCB + tid * 4;
    int v0, v1, v2, v3;
    scan_load4(base, n, v0, v1, v2, v3);
    int s = v0 + v1 + v2 + v3;
    ts[tid] = s;
    __syncthreads();
#pragma unroll
    for (int d = 1; d < 256; d <<= 1) {
        int t = (tid >= d) ? ts[tid - d] : 0;
        __syncthreads();
        ts[tid] += t;
        __syncthreads();
    }
    if (tid == 255) g_bsum[blockIdx.x] = ts[255];
}

// Phase B: one small block scans block sums (exclusive) and writes g_off[n].
__global__ void k_scanB(int nb, int n) {
    __shared__ int bs[SCMAXB];
    int tid = threadIdx.x;
    if (tid < nb) bs[tid] = g_bsum[tid];
    __syncthreads();
    if (tid == 0) {
        int run = 0;
        for (int i = 0; i < nb; i++) {
            int v = bs[i];
            g_boff[i] = run;
            run += v;
        }
        g_off[n] = run;
    }
}

// Phase C: redo block-local scan (L2-hot), add block offset, write off+cursor.
__global__ void k_scanC(int n) {
    __shared__ int ts[256];
    int tid = threadIdx.x;
    int base = blockIdx.x * SCB + tid * 4;
    int v0, v1, v2, v3;
    scan_load4(base, n, v0, v1, v2, v3);
    int s = v0 + v1 + v2 + v3;
    ts[tid] = s;
    __syncthreads();
#pragma unroll
    for (int d = 1; d < 256; d <<= 1) {
        int t = (tid >= d) ? ts[tid - d] : 0;
        __syncthreads();
        ts[tid] += t;
        __syncthreads();
    }
    int excl = ts[tid] - s + g_boff[blockIdx.x];
    int o0 = excl, o1 = o0 + v0, o2 = o1 + v1, o3 = o2 + v2;
    if (base + 3 < n) {
        *(int4*)(g_off + base)    = make_int4(o0, o1, o2, o3);
        *(int4*)(g_cursor + base) = make_int4(o0, o1, o2, o3);
    } else {
        if (base + 0 < n) { g_off[base + 0] = o0; g_cursor[base + 0] = o0; }
        if (base + 1 < n) { g_off[base + 1] = o1; g_cursor[base + 1] = o1; }
        if (base + 2 < n) { g_off[base + 2] = o2; g_cursor[base + 2] = o2; }
        if (base + 3 < n) { g_off[base + 3] = o3; g_cursor[base + 3] = o3; }
    }
}

// ---------------- CSR fill: group src ids by dst -----------------------------
__global__ void k_fill(const int* __restrict__ ei, int E, int n) {
    int e = blockIdx.x * blockDim.x + threadIdx.x;
    if (e >= E) return;
    int s = ei[e];
    int d = ei[E + e];
    if ((unsigned)s >= (unsigned)n || (unsigned)d >= (unsigned)n) return;
    int pos = atomicAdd(&g_cursor[d], 1);
    g_csr[pos] = s;
}

// ---------------- xw = x @ W_gat^T  (+ per-head attention scalars) -----------
__global__ void k_gemm(const float* __restrict__ x, const float* __restrict__ Wg,
                       const float* __restrict__ attS, const float* __restrict__ attD,
                       int n) {
    __shared__ float xs[16 * 68];
    __shared__ float partS[16][8];
    __shared__ float partD[16][8];
    int tid = threadIdx.x;
    int row0 = blockIdx.x * 16;

    for (int idx = tid; idx < 16 * 64; idx += 256) {
        int r = idx >> 6, f = idx & 63;
        int row = row0 + r;
        xs[r * 68 + f] = (row < n) ? x[row * 64 + f] : 0.f;
    }
    __syncthreads();

    float acc[16];
#pragma unroll
    for (int r = 0; r < 16; r++) acc[r] = 0.f;

    const float4* wrow = (const float4*)(Wg + tid * 64);
#pragma unroll
    for (int fc = 0; fc < 16; fc++) {
        float4 w = wrow[fc];
#pragma unroll
        for (int r = 0; r < 16; r++) {
            float4 xv = *(const float4*)(xs + r * 68 + fc * 4);
            acc[r] = fmaf(w.x, xv.x,
                      fmaf(w.y, xv.y, fmaf(w.z, xv.z, fmaf(w.w, xv.w, acc[r]))));
        }
    }

#pragma unroll
    for (int r = 0; r < 16; r++) {
        int row = row0 + r;
        if (row < n) g_xw[(size_t)row * 256 + tid] = acc[r];
    }

    float aS = attS[tid], aD = attD[tid];
    int wid = tid >> 5, lane = tid & 31;
#pragma unroll
    for (int r = 0; r < 16; r++) {
        float sS = acc[r] * aS, sD = acc[r] * aD;
#pragma unroll
        for (int o = 16; o; o >>= 1) {
            sS += __shfl_xor_sync(0xffffffffu, sS, o);
            sD += __shfl_xor_sync(0xffffffffu, sD, o);
        }
        if (lane == 0) { partS[r][wid] = sS; partD[r][wid] = sD; }
    }
    __syncthreads();
    if (tid < 128) {
        int r = tid >> 3, h = (tid >> 1) & 3, sd = tid & 1;
        int row = row0 + r;
        if (row < n) {
            if (sd == 0) g_as[row * 4 + h] = partS[r][2 * h] + partS[r][2 * h + 1];
            else         g_ad[row * 4 + h] = partD[r][2 * h] + partD[r][2 * h + 1];
        }
    }
}

// ---------------- attention: warp per destination node -----------------------
__global__ void k_attn(int n) {
    __shared__ int ssrc[8][32];
    __shared__ float4 sp[8][32];
    int w = threadIdx.x >> 5, lane = threadIdx.x & 31;
    int i = blockIdx.x * 8 + w;
    if (i >= n) return;

    int off0 = g_off[i];
    int len = g_off[i + 1] - off0;

    const float4* as4 = (const float4*)g_as;
    float4 ad = ((const float4*)g_ad)[i];
    float4 asl = as4[i];

    float self0 = __expf(lrelu(asl.x + ad.x));
    float self1 = __expf(lrelu(asl.y + ad.y));
    float self2 = __expf(lrelu(asl.z + ad.z));
    float self3 = __expf(lrelu(asl.w + ad.w));
    float den0 = (lane == 0) ? self0 : 0.f;
    float den1 = (lane == 0) ? self1 : 0.f;
    float den2 = (lane == 0) ? self2 : 0.f;
    float den3 = (lane == 0) ? self3 : 0.f;

    bool hiHalf = (lane >= 16);
    const float4* xw4 = (const float4*)g_xw;
    const float4* xi = xw4 + (size_t)i * 64 + lane;
    float4 accLo, accHi;
    {
        float wl = hiHalf ? self1 : self0;
        float wh = hiHalf ? self3 : self2;
        float4 vl = xi[0], vh = xi[32];
        accLo = make_float4(wl * vl.x, wl * vl.y, wl * vl.z, wl * vl.w);
        accHi = make_float4(wh * vh.x, wh * vh.y, wh * vh.z, wh * vh.w);
    }

    for (int base = 0; base < len; base += 32) {
        int k = base + lane;
        if (k < len) {
            int s = g_csr[off0 + k];
            float4 a = as4[s];
            float p0 = __expf(lrelu(a.x + ad.x));
            float p1 = __expf(lrelu(a.y + ad.y));
            float p2 = __expf(lrelu(a.z + ad.z));
            float p3 = __expf(lrelu(a.w + ad.w));
            den0 += p0; den1 += p1; den2 += p2; den3 += p3;
            ssrc[w][lane] = s;
            sp[w][lane] = make_float4(p0, p1, p2, p3);
        }
        __syncwarp();
        int cnt = min(32, len - base);
#pragma unroll 4
        for (int t = 0; t < cnt; t++) {
            int s = ssrc[w][t];
            float4 p = sp[w][t];
            const float4* xs4 = xw4 + (size_t)s * 64 + lane;
            float4 vl = xs4[0], vh = xs4[32];
            float pl = hiHalf ? p.y : p.x;
            float ph = hiHalf ? p.w : p.z;
            accLo.x = fmaf(pl, vl.x, accLo.x); accLo.y = fmaf(pl, vl.y, accLo.y);
            accLo.z = fmaf(pl, vl.z, accLo.z); accLo.w = fmaf(pl, vl.w, accLo.w);
            accHi.x = fmaf(ph, vh.x, accHi.x); accHi.y = fmaf(ph, vh.y, accHi.y);
            accHi.z = fmaf(ph, vh.z, accHi.z); accHi.w = fmaf(ph, vh.w, accHi.w);
        }
        __syncwarp();
    }

#pragma unroll
    for (int o = 16; o; o >>= 1) {
        den0 += __shfl_xor_sync(0xffffffffu, den0, o);
        den1 += __shfl_xor_sync(0xffffffffu, den1, o);
        den2 += __shfl_xor_sync(0xffffffffu, den2, o);
        den3 += __shfl_xor_sync(0xffffffffu, den3, o);
    }
    float inv0 = 1.f / (den0 + 1e-16f);
    float inv1 = 1.f / (den1 + 1e-16f);
    float inv2 = 1.f / (den2 + 1e-16f);
    float inv3 = 1.f / (den3 + 1e-16f);
    float invLo = hiHalf ? inv1 : inv0;
    float invHi = hiHalf ? inv3 : inv2;

    float4* go = (float4*)g_gat + (size_t)i * 64 + lane;
    go[0]  = make_float4(accLo.x * invLo, accLo.y * invLo,
                         accLo.z * invLo, accLo.w * invLo);
    go[32] = make_float4(accHi.x * invHi, accHi.y * invHi,
                         accHi.z * invHi, accHi.w * invHi);
}

// ---------------- final: out = ((gat+bias)*mask) @ W_lin^T + b_lin, norm -----
__global__ void k_final(const float* __restrict__ Wl, const float* __restrict__ bg,
                        const float* __restrict__ bl,
                        const int* __restrict__ batch,
                        float* __restrict__ out, int n) {
    __shared__ float grow[32 * 260];
    int tid = threadIdx.x;
    int row0 = blockIdx.x * 32;

    for (int idx = tid; idx < 32 * 256; idx += 256) {
        int r = idx >> 8, c = idx & 255;
        int row = row0 + r;
        float v = 0.f;
        if (row < n) {
            unsigned int mb = g_mbits[row * 2 + ((c >> 5) & 1)];
            float bit = (float)((mb >> (c & 31)) & 1u);
            v = (g_gat[(size_t)row * 256 + c] + bg[c]) * bit;
        }
        grow[r * 260 + c] = v;
    }
    __syncthreads();

    int d2 = tid & 63, rg = tid >> 6;
    float acc[8];
#pragma unroll
    for (int k = 0; k < 8; k++) acc[k] = 0.f;

    const float4* wl4 = (const float4*)(Wl + d2 * 256);
#pragma unroll 4
    for (int c4 = 0; c4 < 64; c4++) {
        float4 wv = wl4[c4];
#pragma unroll
        for (int k = 0; k < 8; k++) {
            float4 g = *(const float4*)(grow + (rg * 8 + k) * 260 + c4 * 4);
            acc[k] = fmaf(wv.x, g.x,
                      fmaf(wv.y, g.y, fmaf(wv.z, g.z, fmaf(wv.w, g.w, acc[k]))));
        }
    }

    float b = bl[d2];
#pragma unroll
    for (int k = 0; k < 8; k++) {
        int row = row0 + rg * 8 + k;
        if (row < n) {
            int bi = batch[row];
            int dd = (bi >= 0 && bi < GMAXG) ? g_deg[bi] : 0;
            float dv = (dd > 0) ? (float)dd : 1.f;
            out[row * 64 + d2] = (acc[k] + b) * rsqrtf(dv);
        }
    }
}

// ---------------- launcher ----------------------------------------------------
extern "C" void kernel_launch(void* const* d_in, const int* in_sizes, int n_in,
                              void* d_out, int out_size) {
    const float* x     = (const float*)d_in[0];
    const float* mask  = (const float*)d_in[1];
    const int*   ei    = (const int*)d_in[2];
    const int*   batch = (const int*)d_in[3];
    const float* Wg    = (const float*)d_in[4];
    const float* attS  = (const float*)d_in[5];
    const float* attD  = (const float*)d_in[6];
    const float* bg    = (const float*)d_in[7];
    const float* Wl    = (const float*)d_in[8];
    const float* bl    = (const float*)d_in[9];
    float* out = (float*)d_out;

    int n = in_sizes[0] / 64;
    int E = in_sizes[2] / 2;
    int nb = (n + SCB - 1) / SCB;

    k_nodebits<<<(64 * n + 255) / 256, 256>>>(mask, n);
    k_edge1   <<<(E + 255) / 256, 256>>>(ei, E, n);
    k_deg     <<<128, 256>>>(batch, n);
    k_scanA   <<<nb, 256>>>(n);
    k_scanB   <<<1, 64>>>(nb, n);
    k_scanC   <<<nb, 256>>>(n);
    k_fill    <<<(E + 255) / 256, 256>>>(ei, E, n);
    k_gemm    <<<(n + 15) / 16, 256>>>(x, Wg, attS, attD, n);
    k_attn    <<<(n + 7) / 8, 256>>>(n);
    k_final   <<<(n + 31) / 32, 256>>>(Wl, bg, bl, batch, out, n);
}

// round 11
// speedup vs baseline: 1.3222x; 1.0643x over previous
#include <cuda_runtime.h>
#include <cuda_bf16.h>
#include <cuda_fp16.h>

// Problem constants (fixed by the dataset)
#define NMAX 50000
#define EMAX 800000
#define GMAXG 64
#define SCB 1024                 // elements per scan block
#define SCMAXB ((NMAX + SCB - 1) / SCB)

// ---------------- scratch (device globals; no allocation allowed) -------------
__device__ __align__(8) unsigned int g_mbits[2 * NMAX];     // result mask bits
__device__ __align__(8) unsigned int g_nodebits[2 * NMAX];  // mask[n,f]>0 bits
__device__ __align__(16) int g_cnt[NMAX];
__device__ __align__(16) int g_off[NMAX + 4];
__device__ __align__(16) int g_cursor[NMAX];
__device__ int g_bsum[SCMAXB];
__device__ int g_boff[SCMAXB];
__device__ int g_csr[EMAX];                    // src ids grouped by dst
__device__ __align__(16) __half g_xwh[(size_t)NMAX * 256];  // fp16 features
__device__ __align__(16) float g_gat[(size_t)NMAX * 256];
__device__ __align__(16) float g_as[NMAX * 4];
__device__ __align__(16) float g_ad[NMAX * 4];
__device__ int g_deg[GMAXG];

__device__ __forceinline__ float lrelu(float a) { return fmaxf(a, 0.2f * a); }
__device__ __forceinline__ float2 h2f(unsigned int u) {
    __half2 h = *reinterpret_cast<const __half2*>(&u);
    return __half22float2(h);
}

// ---------------- nodebits + zero all accumulators ---------------------------
__global__ void k_nodebits(const float* __restrict__ mask, int n) {
    int t = blockIdx.x * blockDim.x + threadIdx.x;
    if (t < n) g_cnt[t] = 0;
    if (t < GMAXG) g_deg[t] = 0;
    int gw = t >> 5;
    int lane = threadIdx.x & 31;
    int node = gw >> 1, half = gw & 1;
    if (node >= n) return;
    float v = mask[node * 64 + half * 32 + lane];
    unsigned int b = __ballot_sync(0xffffffffu, v > 0.f);
    if (lane == 0) {
        g_nodebits[node * 2 + half] = b;
        g_mbits[node * 2 + half] = 0u;
    }
}

// ---------------- per-edge: 64-bit mask OR-scatter + in-degree count ---------
__global__ void k_edge1(const int* __restrict__ ei, int E, int n) {
    int e = blockIdx.x * blockDim.x + threadIdx.x;
    if (e >= E) return;
    int r = ei[e];       // edge_index[0] = row (mask target) = GAT src
    int c = ei[E + e];   // edge_index[1] = col (mask source) = GAT dst
    if ((unsigned)r >= (unsigned)n || (unsigned)c >= (unsigned)n) return;
    unsigned long long nb = ((const unsigned long long*)g_nodebits)[c];
    atomicOr((unsigned long long*)g_mbits + r, nb);
    atomicAdd(&g_cnt[c], 1);
}

// ---------------- graph-size histogram (batch_idx -> deg) --------------------
__global__ void k_deg(const int* __restrict__ batch, int n) {
    __shared__ int h[GMAXG];
    if (threadIdx.x < GMAXG) h[threadIdx.x] = 0;
    __syncthreads();
    for (int i = blockIdx.x * blockDim.x + threadIdx.x; i < n;
         i += gridDim.x * blockDim.x) {
        int b = batch[i];
        if (b >= 0 && b < GMAXG) atomicAdd(&h[b], 1);
    }
    __syncthreads();
    if (threadIdx.x < GMAXG) atomicAdd(&g_deg[threadIdx.x], h[threadIdx.x]);
}

// ---------------- multi-block exclusive scan of g_cnt -> g_off/g_cursor ------
__device__ __forceinline__ void scan_load4(int base, int n,
                                           int& v0, int& v1, int& v2, int& v3) {
    v0 = v1 = v2 = v3 = 0;
    if (base + 3 < n) {
        int4 c = *(const int4*)(g_cnt + base);
        v0 = c.x; v1 = c.y; v2 = c.z; v3 = c.w;
    } else {
        if (base + 0 < n) v0 = g_cnt[base + 0];
        if (base + 1 < n) v1 = g_cnt[base + 1];
        if (base + 2 < n) v2 = g_cnt[base + 2];
        if (base + 3 < n) v3 = g_cnt[base + 3];
    }
}

__global__ void k_scanA(int n) {
    __shared__ int ts[256];
    int tid = threadIdx.x;
    int base = blockIdx.x * SCB + tid * 4;
    int v0, v1, v2, v3;
    scan_load4(base, n, v0, v1, v2, v3);
    int s = v0 + v1 + v2 + v3;
    ts[tid] = s;
    __syncthreads();
#pragma unroll
    for (int d = 1; d < 256; d <<= 1) {
        int t = (tid >= d) ? ts[tid - d] : 0;
        __syncthreads();
        ts[tid] += t;
        __syncthreads();
    }
    if (tid == 255) g_bsum[blockIdx.x] = ts[255];
}

__global__ void k_scanB(int nb, int n) {
    __shared__ int bs[SCMAXB];
    int tid = threadIdx.x;
    if (tid < nb) bs[tid] = g_bsum[tid];
    __syncthreads();
    if (tid == 0) {
        int run = 0;
        for (int i = 0; i < nb; i++) {
            int v = bs[i];
            g_boff[i] = run;
            run += v;
        }
        g_off[n] = run;
    }
}

__global__ void k_scanC(int n) {
    __shared__ int ts[256];
    int tid = threadIdx.x;
    int base = blockIdx.x * SCB + tid * 4;
    int v0, v1, v2, v3;
    scan_load4(base, n, v0, v1, v2, v3);
    int s = v0 + v1 + v2 + v3;
    ts[tid] = s;
    __syncthreads();
#pragma unroll
    for (int d = 1; d < 256; d <<= 1) {
        int t = (tid >= d) ? ts[tid - d] : 0;
        __syncthreads();
        ts[tid] += t;
        __syncthreads();
    }
    int excl = ts[tid] - s + g_boff[blockIdx.x];
    int o0 = excl, o1 = o0 + v0, o2 = o1 + v1, o3 = o2 + v2;
    if (base + 3 < n) {
        *(int4*)(g_off + base)    = make_int4(o0, o1, o2, o3);
        *(int4*)(g_cursor + base) = make_int4(o0, o1, o2, o3);
    } else {
        if (base + 0 < n) { g_off[base + 0] = o0; g_cursor[base + 0] = o0; }
        if (base + 1 < n) { g_off[base + 1] = o1; g_cursor[base + 1] = o1; }
        if (base + 2 < n) { g_off[base + 2] = o2; g_cursor[base + 2] = o2; }
        if (base + 3 < n) { g_off[base + 3] = o3; g_cursor[base + 3] = o3; }
    }
}

// ---------------- CSR fill: group src ids by dst -----------------------------
__global__ void k_fill(const int* __restrict__ ei, int E, int n) {
    int e = blockIdx.x * blockDim.x + threadIdx.x;
    if (e >= E) return;
    int s = ei[e];
    int d = ei[E + e];
    if ((unsigned)s >= (unsigned)n || (unsigned)d >= (unsigned)n) return;
    int pos = atomicAdd(&g_cursor[d], 1);
    g_csr[pos] = s;
}

// ---------------- xw = x @ W_gat^T  (+ per-head attention scalars) -----------
// 256 threads, 16 rows per block. Thread t owns output channel t for 16 rows.
// Features stored fp16 (gather operand); attention scalars computed in fp32.
__global__ void k_gemm(const float* __restrict__ x, const float* __restrict__ Wg,
                       const float* __restrict__ attS, const float* __restrict__ attD,
                       int n) {
    __shared__ float xs[16 * 68];
    __shared__ float partS[16][8];
    __shared__ float partD[16][8];
    int tid = threadIdx.x;
    int row0 = blockIdx.x * 16;

    for (int idx = tid; idx < 16 * 64; idx += 256) {
        int r = idx >> 6, f = idx & 63;
        int row = row0 + r;
        xs[r * 68 + f] = (row < n) ? x[row * 64 + f] : 0.f;
    }
    __syncthreads();

    float acc[16];
#pragma unroll
    for (int r = 0; r < 16; r++) acc[r] = 0.f;

    const float4* wrow = (const float4*)(Wg + tid * 64);
#pragma unroll
    for (int fc = 0; fc < 16; fc++) {
        float4 w = wrow[fc];
#pragma unroll
        for (int r = 0; r < 16; r++) {
            float4 xv = *(const float4*)(xs + r * 68 + fc * 4);
            acc[r] = fmaf(w.x, xv.x,
                      fmaf(w.y, xv.y, fmaf(w.z, xv.z, fmaf(w.w, xv.w, acc[r]))));
        }
    }

#pragma unroll
    for (int r = 0; r < 16; r++) {
        int row = row0 + r;
        if (row < n) g_xwh[(size_t)row * 256 + tid] = __float2half(acc[r]);
    }

    float aS = attS[tid], aD = attD[tid];
    int wid = tid >> 5, lane = tid & 31;
#pragma unroll
    for (int r = 0; r < 16; r++) {
        float sS = acc[r] * aS, sD = acc[r] * aD;
#pragma unroll
        for (int o = 16; o; o >>= 1) {
            sS += __shfl_xor_sync(0xffffffffu, sS, o);
            sD += __shfl_xor_sync(0xffffffffu, sD, o);
        }
        if (lane == 0) { partS[r][wid] = sS; partD[r][wid] = sD; }
    }
    __syncthreads();
    if (tid < 128) {
        int r = tid >> 3, h = (tid >> 1) & 3, sd = tid & 1;
        int row = row0 + r;
        if (row < n) {
            if (sd == 0) g_as[row * 4 + h] = partS[r][2 * h] + partS[r][2 * h + 1];
            else         g_ad[row * 4 + h] = partD[r][2 * h] + partD[r][2 * h + 1];
        }
    }
}

// ---------------- attention: warp per destination node -----------------------
// Lane owns channels 8*lane..8*lane+7 (head = lane>>3); one LDG.128 per edge.
__global__ void k_attn(int n) {
    __shared__ int ssrc[8][32];
    __shared__ float4 sp[8][32];
    int w = threadIdx.x >> 5, lane = threadIdx.x & 31;
    int i = blockIdx.x * 8 + w;
    if (i >= n) return;

    int off0 = g_off[i];
    int len = g_off[i + 1] - off0;

    const float4* as4 = (const float4*)g_as;
    float4 ad = ((const float4*)g_ad)[i];
    float4 asl = as4[i];

    float self0 = __expf(lrelu(asl.x + ad.x));
    float self1 = __expf(lrelu(asl.y + ad.y));
    float self2 = __expf(lrelu(asl.z + ad.z));
    float self3 = __expf(lrelu(asl.w + ad.w));
    float den0 = (lane == 0) ? self0 : 0.f;
    float den1 = (lane == 0) ? self1 : 0.f;
    float den2 = (lane == 0) ? self2 : 0.f;
    float den3 = (lane == 0) ? self3 : 0.f;

    int h = lane >> 3;   // head owned by this lane's channels
    float selfh = (h == 0) ? self0 : (h == 1) ? self1 : (h == 2) ? self2 : self3;

    const uint4* xwh = (const uint4*)g_xwh;   // 32 x uint4 (8 halves) per node
    float a0, a1, a2, a3, a4, a5, a6, a7;
    {
        uint4 v = xwh[(size_t)i * 32 + lane];
        float2 f0 = h2f(v.x), f1 = h2f(v.y), f2 = h2f(v.z), f3 = h2f(v.w);
        a0 = selfh * f0.x; a1 = selfh * f0.y;
        a2 = selfh * f1.x; a3 = selfh * f1.y;
        a4 = selfh * f2.x; a5 = selfh * f2.y;
        a6 = selfh * f3.x; a7 = selfh * f3.y;
    }

    for (int base = 0; base < len; base += 32) {
        int k = base + lane;
        if (k < len) {
            int s = g_csr[off0 + k];
            float4 a = as4[s];
            float p0 = __expf(lrelu(a.x + ad.x));
            float p1 = __expf(lrelu(a.y + ad.y));
            float p2 = __expf(lrelu(a.z + ad.z));
            float p3 = __expf(lrelu(a.w + ad.w));
            den0 += p0; den1 += p1; den2 += p2; den3 += p3;
            ssrc[w][lane] = s;
            sp[w][lane] = make_float4(p0, p1, p2, p3);
        }
        __syncwarp();
        int cnt = min(32, len - base);
#pragma unroll 4
        for (int t = 0; t < cnt; t++) {
            int s = ssrc[w][t];
            float p = ((const float*)&sp[w][t])[h];
            uint4 v = xwh[(size_t)s * 32 + lane];
            float2 f0 = h2f(v.x), f1 = h2f(v.y), f2 = h2f(v.z), f3 = h2f(v.w);
            a0 = fmaf(p, f0.x, a0); a1 = fmaf(p, f0.y, a1);
            a2 = fmaf(p, f1.x, a2); a3 = fmaf(p, f1.y, a3);
            a4 = fmaf(p, f2.x, a4); a5 = fmaf(p, f2.y, a5);
            a6 = fmaf(p, f3.x, a6); a7 = fmaf(p, f3.y, a7);
        }
        __syncwarp();
    }

#pragma unroll
    for (int o = 16; o; o >>= 1) {
        den0 += __shfl_xor_sync(0xffffffffu, den0, o);
        den1 += __shfl_xor_sync(0xffffffffu, den1, o);
        den2 += __shfl_xor_sync(0xffffffffu, den2, o);
        den3 += __shfl_xor_sync(0xffffffffu, den3, o);
    }
    float inv0 = 1.f / (den0 + 1e-16f);
    float inv1 = 1.f / (den1 + 1e-16f);
    float inv2 = 1.f / (den2 + 1e-16f);
    float inv3 = 1.f / (den3 + 1e-16f);
    float invh = (h == 0) ? inv0 : (h == 1) ? inv1 : (h == 2) ? inv2 : inv3;

    float4* go = (float4*)g_gat + (size_t)i * 64 + lane * 2;
    go[0] = make_float4(a0 * invh, a1 * invh, a2 * invh, a3 * invh);
    go[1] = make_float4(a4 * invh, a5 * invh, a6 * invh, a7 * invh);
}

// ---------------- final: out = ((gat+bias)*mask) @ W_lin^T + b_lin, norm -----
__global__ void k_final(const float* __restrict__ Wl, const float* __restrict__ bg,
                        const float* __restrict__ bl,
                        const int* __restrict__ batch,
                        float* __restrict__ out, int n) {
    __shared__ float grow[32 * 260];
    int tid = threadIdx.x;
    int row0 = blockIdx.x * 32;

    for (int idx = tid; idx < 32 * 256; idx += 256) {
        int r = idx >> 8, c = idx & 255;
        int row = row0 + r;
        float v = 0.f;
        if (row < n) {
            unsigned int mb = g_mbits[row * 2 + ((c >> 5) & 1)];
            float bit = (float)((mb >> (c & 31)) & 1u);
            v = (g_gat[(size_t)row * 256 + c] + bg[c]) * bit;
        }
        grow[r * 260 + c] = v;
    }
    __syncthreads();

    int d2 = tid & 63, rg = tid >> 6;
    float acc[8];
#pragma unroll
    for (int k = 0; k < 8; k++) acc[k] = 0.f;

    const float4* wl4 = (const float4*)(Wl + d2 * 256);
#pragma unroll 4
    for (int c4 = 0; c4 < 64; c4++) {
        float4 wv = wl4[c4];
#pragma unroll
        for (int k = 0; k < 8; k++) {
            float4 g = *(const float4*)(grow + (rg * 8 + k) * 260 + c4 * 4);
            acc[k] = fmaf(wv.x, g.x,
                      fmaf(wv.y, g.y, fmaf(wv.z, g.z, fmaf(wv.w, g.w, acc[k]))));
        }
    }

    float b = bl[d2];
#pragma unroll
    for (int k = 0; k < 8; k++) {
        int row = row0 + rg * 8 + k;
        if (row < n) {
            int bi = batch[row];
            int dd = (bi >= 0 && bi < GMAXG) ? g_deg[bi] : 0;
            float dv = (dd > 0) ? (float)dd : 1.f;
            out[row * 64 + d2] = (acc[k] + b) * rsqrtf(dv);
        }
    }
}

// ---------------- launcher ----------------------------------------------------
extern "C" void kernel_launch(void* const* d_in, const int* in_sizes, int n_in,
                              void* d_out, int out_size) {
    const float* x     = (const float*)d_in[0];
    const float* mask  = (const float*)d_in[1];
    const int*   ei    = (const int*)d_in[2];
    const int*   batch = (const int*)d_in[3];
    const float* Wg    = (const float*)d_in[4];
    const float* attS  = (const float*)d_in[5];
    const float* attD  = (const float*)d_in[6];
    const float* bg    = (const float*)d_in[7];
    const float* Wl    = (const float*)d_in[8];
    const float* bl    = (const float*)d_in[9];
    float* out = (float*)d_out;

    int n = in_sizes[0] / 64;
    int E = in_sizes[2] / 2;
    int nb = (n + SCB - 1) / SCB;

    k_nodebits<<<(64 * n + 255) / 256, 256>>>(mask, n);
    k_edge1   <<<(E + 255) / 256, 256>>>(ei, E, n);
    k_deg     <<<128, 256>>>(batch, n);
    k_scanA   <<<nb, 256>>>(n);
    k_scanB   <<<1, 64>>>(nb, n);
    k_scanC   <<<nb, 256>>>(n);
    k_fill    <<<(E + 255) / 256, 256>>>(ei, E, n);
    k_gemm    <<<(n + 15) / 16, 256>>>(x, Wg, attS, attD, n);
    k_attn    <<<(n + 7) / 8, 256>>>(n);
    k_final   <<<(n + 31) / 32, 256>>>(Wl, bg, bl, batch, out, n);
}

// round 13
// speedup vs baseline: 1.3303x; 1.0061x over previous
#include <cuda_runtime.h>
#include <cuda_bf16.h>
#include <cuda_fp16.h>

// Problem constants (fixed by the dataset)
#define NMAX 50000
#define EMAX 800000
#define GMAXG 64
#define SCB 1024                 // elements per scan block
#define SCMAXB ((NMAX + SCB - 1) / SCB)

// ---------------- scratch (device globals; no allocation allowed) -------------
__device__ __align__(8) unsigned int g_mbits[2 * NMAX];     // result mask bits
__device__ __align__(8) unsigned int g_nodebits[2 * NMAX];  // mask[n,f]>0 bits
__device__ __align__(16) int g_cnt[NMAX];
__device__ __align__(16) int g_off[NMAX + 4];
__device__ __align__(16) int g_cursor[NMAX];
__device__ int g_bsum[SCMAXB];
__device__ int g_boff[SCMAXB];
__device__ int g_csr[EMAX];                    // src ids grouped by dst
__device__ __align__(16) __half g_xwh[(size_t)NMAX * 256];  // fp16 features
__device__ __align__(16) __half g_gath[(size_t)NMAX * 256]; // fp16 (gat+b)*mask
__device__ __align__(16) float g_as[NMAX * 4];
__device__ __align__(16) float g_ad[NMAX * 4];
__device__ int g_deg[GMAXG];

__device__ __forceinline__ float lrelu(float a) { return fmaxf(a, 0.2f * a); }
__device__ __forceinline__ float2 h2f(unsigned int u) {
    __half2 h = *reinterpret_cast<const __half2*>(&u);
    return __half22float2(h);
}
// packed fp32x2 FMA: d = a*b + d  (PTX ISA 8.6, sm_100+)
__device__ __forceinline__ void fma2(unsigned long long& d,
                                     unsigned long long a,
                                     unsigned long long b) {
    asm("fma.rn.f32x2 %0, %1, %2, %0;" : "+l"(d) : "l"(a), "l"(b));
}
__device__ __forceinline__ float2 unpk(unsigned long long p) {
    float x, y;
    asm("mov.b64 {%0, %1}, %2;" : "=f"(x), "=f"(y) : "l"(p));
    return make_float2(x, y);
}

// ---------------- nodebits + zero count accumulators --------------------------
__global__ void k_nodebits(const float* __restrict__ mask, int n) {
    int t = blockIdx.x * blockDim.x + threadIdx.x;
    if (t < n) g_cnt[t] = 0;
    int gw = t >> 5;
    int lane = threadIdx.x & 31;
    int node = gw >> 1, half = gw & 1;
    if (node >= n) return;
    float v = mask[node * 64 + half * 32 + lane];
    unsigned int b = __ballot_sync(0xffffffffu, v > 0.f);
    if (lane == 0) {
        g_nodebits[node * 2 + half] = b;
        g_mbits[node * 2 + half] = 0u;
    }
}

// ---------------- per-edge: in-degree count only ------------------------------
__global__ void k_edge1(const int* __restrict__ ei, int E, int n) {
    int e = blockIdx.x * blockDim.x + threadIdx.x;
    if (e >= E) return;
    int c = ei[E + e];   // edge_index[1] = dst
    if ((unsigned)c >= (unsigned)n) return;
    atomicAdd(&g_cnt[c], 1);
}

// ---------------- multi-block exclusive scan of g_cnt -> g_off/g_cursor ------
__device__ __forceinline__ void scan_load4(int base, int n,
                                           int& v0, int& v1, int& v2, int& v3) {
    v0 = v1 = v2 = v3 = 0;
    if (base + 3 < n) {
        int4 c = *(const int4*)(g_cnt + base);
        v0 = c.x; v1 = c.y; v2 = c.z; v3 = c.w;
    } else {
        if (base + 0 < n) v0 = g_cnt[base + 0];
        if (base + 1 < n) v1 = g_cnt[base + 1];
        if (base + 2 < n) v2 = g_cnt[base + 2];
        if (base + 3 < n) v3 = g_cnt[base + 3];
    }
}

__global__ void k_scanA(int n) {
    __shared__ int ts[256];
    int tid = threadIdx.x;
    int base = blockIdx.x * SCB + tid * 4;
    int v0, v1, v2, v3;
    scan_load4(base, n, v0, v1, v2, v3);
    int s = v0 + v1 + v2 + v3;
    ts[tid] = s;
    __syncthreads();
#pragma unroll
    for (int d = 1; d < 256; d <<= 1) {
        int t = (tid >= d) ? ts[tid - d] : 0;
        __syncthreads();
        ts[tid] += t;
        __syncthreads();
    }
    if (tid == 255) g_bsum[blockIdx.x] = ts[255];
}

// Phase B: scan block sums; also compute graph sizes by binary search
// (batch_idx is sorted by construction).
__global__ void k_scanB(int nb, int n, const int* __restrict__ batch) {
    __shared__ int bs[SCMAXB];
    int tid = threadIdx.x;
    if (tid < nb) bs[tid] = g_bsum[tid];
    __syncthreads();
    if (tid == 0) {
        int run = 0;
        for (int i = 0; i < nb; i++) {
            int v = bs[i];
            g_boff[i] = run;
            run += v;
        }
        g_off[n] = run;
    }
    if (tid < GMAXG) {
        int lo = 0, hi = n;
        while (lo < hi) { int m = (lo + hi) >> 1; if (batch[m] < tid) lo = m + 1; else hi = m; }
        int lob = lo;
        hi = n;
        while (lo < hi) { int m = (lo + hi) >> 1; if (batch[m] <= tid) lo = m + 1; else hi = m; }
        g_deg[tid] = lo - lob;
    }
}

__global__ void k_scanC(int n) {
    __shared__ int ts[256];
    int tid = threadIdx.x;
    int base = blockIdx.x * SCB + tid * 4;
    int v0, v1, v2, v3;
    scan_load4(base, n, v0, v1, v2, v3);
    int s = v0 + v1 + v2 + v3;
    ts[tid] = s;
    __syncthreads();
#pragma unroll
    for (int d = 1; d < 256; d <<= 1) {
        int t = (tid >= d) ? ts[tid - d] : 0;
        __syncthreads();
        ts[tid] += t;
        __syncthreads();
    }
    int excl = ts[tid] - s + g_boff[blockIdx.x];
    int o0 = excl, o1 = o0 + v0, o2 = o1 + v1, o3 = o2 + v2;
    if (base + 3 < n) {
        *(int4*)(g_off + base)    = make_int4(o0, o1, o2, o3);
        *(int4*)(g_cursor + base) = make_int4(o0, o1, o2, o3);
    } else {
        if (base + 0 < n) { g_off[base + 0] = o0; g_cursor[base + 0] = o0; }
        if (base + 1 < n) { g_off[base + 1] = o1; g_cursor[base + 1] = o1; }
        if (base + 2 < n) { g_off[base + 2] = o2; g_cursor[base + 2] = o2; }
        if (base + 3 < n) { g_off[base + 3] = o3; g_cursor[base + 3] = o3; }
    }
}

// ---------------- CSR fill + 64-bit mask OR-scatter ---------------------------
__global__ void k_fill(const int* __restrict__ ei, int E, int n) {
    int e = blockIdx.x * blockDim.x + threadIdx.x;
    if (e >= E) return;
    int s = ei[e];           // edge_index[0] = src (mask target)
    int d = ei[E + e];       // edge_index[1] = dst (mask source)
    if ((unsigned)s >= (unsigned)n || (unsigned)d >= (unsigned)n) return;
    unsigned long long nb = ((const unsigned long long*)g_nodebits)[d];
    atomicOr((unsigned long long*)g_mbits + s, nb);
    int pos = atomicAdd(&g_cursor[d], 1);
    g_csr[pos] = s;
}

// ---------------- xw = x @ W_gat^T  (+ per-head attention scalars) -----------
// 256 threads, 16 rows per block; packed f32x2 FMA over the K dimension.
__global__ void k_gemm(const float* __restrict__ x, const float* __restrict__ Wg,
                       const float* __restrict__ attS, const float* __restrict__ attD,
                       int n) {
    __shared__ float xs[16 * 68];
    __shared__ float partS[16][8];
    __shared__ float partD[16][8];
    int tid = threadIdx.x;
    int row0 = blockIdx.x * 16;

    for (int idx = tid; idx < 16 * 64; idx += 256) {
        int r = idx >> 6, f = idx & 63;
        int row = row0 + r;
        xs[r * 68 + f] = (row < n) ? x[row * 64 + f] : 0.f;
    }
    __syncthreads();

    unsigned long long accp[16];
#pragma unroll
    for (int r = 0; r < 16; r++) accp[r] = 0ull;

    const ulonglong2* wrow = (const ulonglong2*)(Wg + tid * 64);
#pragma unroll
    for (int fc = 0; fc < 16; fc++) {
        ulonglong2 w = wrow[fc];
#pragma unroll
        for (int r = 0; r < 16; r++) {
            ulonglong2 xv = *(const ulonglong2*)(xs + r * 68 + fc * 4);
            fma2(accp[r], w.x, xv.x);
            fma2(accp[r], w.y, xv.y);
        }
    }

    float acc[16];
#pragma unroll
    for (int r = 0; r < 16; r++) {
        float2 u = unpk(accp[r]);
        acc[r] = u.x + u.y;
    }

#pragma unroll
    for (int r = 0; r < 16; r++) {
        int row = row0 + r;
        if (row < n) g_xwh[(size_t)row * 256 + tid] = __float2half(acc[r]);
    }

    float aS = attS[tid], aD = attD[tid];
    int wid = tid >> 5, lane = tid & 31;
#pragma unroll
    for (int r = 0; r < 16; r++) {
        float sS = acc[r] * aS, sD = acc[r] * aD;
#pragma unroll
        for (int o = 16; o; o >>= 1) {
            sS += __shfl_xor_sync(0xffffffffu, sS, o);
            sD += __shfl_xor_sync(0xffffffffu, sD, o);
        }
        if (lane == 0) { partS[r][wid] = sS; partD[r][wid] = sD; }
    }
    __syncthreads();
    if (tid < 128) {
        int r = tid >> 3, h = (tid >> 1) & 3, sd = tid & 1;
        int row = row0 + r;
        if (row < n) {
            if (sd == 0) g_as[row * 4 + h] = partS[r][2 * h] + partS[r][2 * h + 1];
            else         g_ad[row * 4 + h] = partD[r][2 * h] + partD[r][2 * h + 1];
        }
    }
}

// ---------------- attention: warp per destination node -----------------------
// Lane owns channels 8*lane..8*lane+7 (head = lane>>3); one LDG.128 per edge.
// Epilogue applies bias + mask and stores fp16.
__global__ void k_attn(const float* __restrict__ bg, int n) {
    __shared__ int ssrc[8][32];
    __shared__ float4 sp[8][32];
    int w = threadIdx.x >> 5, lane = threadIdx.x & 31;
    int i = blockIdx.x * 8 + w;
    if (i >= n) return;

    int off0 = g_off[i];
    int len = g_off[i + 1] - off0;

    const float4* as4 = (const float4*)g_as;
    float4 ad = ((const float4*)g_ad)[i];
    float4 asl = as4[i];

    float self0 = __expf(lrelu(asl.x + ad.x));
    float self1 = __expf(lrelu(asl.y + ad.y));
    float self2 = __expf(lrelu(asl.z + ad.z));
    float self3 = __expf(lrelu(asl.w + ad.w));
    float den0 = (lane == 0) ? self0 : 0.f;
    float den1 = (lane == 0) ? self1 : 0.f;
    float den2 = (lane == 0) ? self2 : 0.f;
    float den3 = (lane == 0) ? self3 : 0.f;

    int h = lane >> 3;   // head owned by this lane's channels
    float selfh = (h == 0) ? self0 : (h == 1) ? self1 : (h == 2) ? self2 : self3;

    const uint4* xwh = (const uint4*)g_xwh;   // 32 x uint4 (8 halves) per node
    float a0, a1, a2, a3, a4, a5, a6, a7;
    {
        uint4 v = xwh[(size_t)i * 32 + lane];
        float2 f0 = h2f(v.x), f1 = h2f(v.y), f2 = h2f(v.z), f3 = h2f(v.w);
        a0 = selfh * f0.x; a1 = selfh * f0.y;
        a2 = selfh * f1.x; a3 = selfh * f1.y;
        a4 = selfh * f2.x; a5 = selfh * f2.y;
        a6 = selfh * f3.x; a7 = selfh * f3.y;
    }

    for (int base = 0; base < len; base += 32) {
        int k = base + lane;
        if (k < len) {
            int s = g_csr[off0 + k];
            float4 a = as4[s];
            float p0 = __expf(lrelu(a.x + ad.x));
            float p1 = __expf(lrelu(a.y + ad.y));
            float p2 = __expf(lrelu(a.z + ad.z));
            float p3 = __expf(lrelu(a.w + ad.w));
            den0 += p0; den1 += p1; den2 += p2; den3 += p3;
            ssrc[w][lane] = s;
            sp[w][lane] = make_float4(p0, p1, p2, p3);
        }
        __syncwarp();
        int cnt = min(32, len - base);
#pragma unroll 4
        for (int t = 0; t < cnt; t++) {
            int s = ssrc[w][t];
            float p = ((const float*)&sp[w][t])[h];
            uint4 v = xwh[(size_t)s * 32 + lane];
            float2 f0 = h2f(v.x), f1 = h2f(v.y), f2 = h2f(v.z), f3 = h2f(v.w);
            a0 = fmaf(p, f0.x, a0); a1 = fmaf(p, f0.y, a1);
            a2 = fmaf(p, f1.x, a2); a3 = fmaf(p, f1.y, a3);
            a4 = fmaf(p, f2.x, a4); a5 = fmaf(p, f2.y, a5);
            a6 = fmaf(p, f3.x, a6); a7 = fmaf(p, f3.y, a7);
        }
        __syncwarp();
    }

#pragma unroll
    for (int o = 16; o; o >>= 1) {
        den0 += __shfl_xor_sync(0xffffffffu, den0, o);
        den1 += __shfl_xor_sync(0xffffffffu, den1, o);
        den2 += __shfl_xor_sync(0xffffffffu, den2, o);
        den3 += __shfl_xor_sync(0xffffffffu, den3, o);
    }
    float inv0 = 1.f / (den0 + 1e-16f);
    float inv1 = 1.f / (den1 + 1e-16f);
    float inv2 = 1.f / (den2 + 1e-16f);
    float inv3 = 1.f / (den3 + 1e-16f);
    float invh = (h == 0) ? inv0 : (h == 1) ? inv1 : (h == 2) ? inv2 : inv3;

    // epilogue: (acc*inv + bias) * maskbit, store fp16
    const float4* bg4 = (const float4*)(bg + lane * 8);
    float4 b0 = bg4[0], b1 = bg4[1];
    unsigned long long mb = ((const unsigned long long*)g_mbits)[i];
    int bbase = 8 * (lane & 7);
    float r0 = (a0 * invh + b0.x) * (float)((mb >> (bbase + 0)) & 1);
    float r1 = (a1 * invh + b0.y) * (float)((mb >> (bbase + 1)) & 1);
    float r2 = (a2 * invh + b0.z) * (float)((mb >> (bbase + 2)) & 1);
    float r3 = (a3 * invh + b0.w) * (float)((mb >> (bbase + 3)) & 1);
    float r4 = (a4 * invh + b1.x) * (float)((mb >> (bbase + 4)) & 1);
    float r5 = (a5 * invh + b1.y) * (float)((mb >> (bbase + 5)) & 1);
    float r6 = (a6 * invh + b1.z) * (float)((mb >> (bbase + 6)) & 1);
    float r7 = (a7 * invh + b1.w) * (float)((mb >> (bbase + 7)) & 1);

    uint4 o;
    __half2 h0 = __floats2half2_rn(r0, r1);
    __half2 h1 = __floats2half2_rn(r2, r3);
    __half2 h2 = __floats2half2_rn(r4, r5);
    __half2 h3 = __floats2half2_rn(r6, r7);
    o.x = *(unsigned int*)&h0;
    o.y = *(unsigned int*)&h1;
    o.z = *(unsigned int*)&h2;
    o.w = *(unsigned int*)&h3;
    ((uint4*)g_gath)[(size_t)i * 32 + lane] = o;
}

// ---------------- final: out = gath @ W_lin^T + b_lin, graph-size norm -------
// 256 threads, 32 rows per block; packed f32x2 FMA over K=256.
__global__ void k_final(const float* __restrict__ Wl,
                        const float* __restrict__ bl,
                        const int* __restrict__ batch,
                        float* __restrict__ out, int n) {
    __shared__ float grow[32 * 260];
    int tid = threadIdx.x;
    int row0 = blockIdx.x * 32;

    const uint4* gh = (const uint4*)g_gath;
    for (int idx = tid; idx < 32 * 32; idx += 256) {
        int r = idx >> 5, u = idx & 31;
        int row = row0 + r;
        uint4 v = make_uint4(0u, 0u, 0u, 0u);
        if (row < n) v = gh[(size_t)row * 32 + u];
        float* dst = grow + r * 260 + u * 8;
        *(float2*)(dst + 0) = h2f(v.x);
        *(float2*)(dst + 2) = h2f(v.y);
        *(float2*)(dst + 4) = h2f(v.z);
        *(float2*)(dst + 6) = h2f(v.w);
    }
    __syncthreads();

    int d2 = tid & 63, rg = tid >> 6;
    unsigned long long accp[8];
#pragma unroll
    for (int k = 0; k < 8; k++) accp[k] = 0ull;

    const ulonglong2* wl2 = (const ulonglong2*)(Wl + d2 * 256);
#pragma unroll 4
    for (int c4 = 0; c4 < 64; c4++) {
        ulonglong2 wv = wl2[c4];
#pragma unroll
        for (int k = 0; k < 8; k++) {
            ulonglong2 g = *(const ulonglong2*)(grow + (rg * 8 + k) * 260 + c4 * 4);
            fma2(accp[k], wv.x, g.x);
            fma2(accp[k], wv.y, g.y);
        }
    }

    float b = bl[d2];
#pragma unroll
    for (int k = 0; k < 8; k++) {
        int row = row0 + rg * 8 + k;
        if (row < n) {
            float2 u = unpk(accp[k]);
            float acc = u.x + u.y;
            int bi = batch[row];
            int dd = (bi >= 0 && bi < GMAXG) ? g_deg[bi] : 0;
            float dv = (dd > 0) ? (float)dd : 1.f;
            out[row * 64 + d2] = (acc + b) * rsqrtf(dv);
        }
    }
}

// ---------------- launcher ----------------------------------------------------
extern "C" void kernel_launch(void* const* d_in, const int* in_sizes, int n_in,
                              void* d_out, int out_size) {
    const float* x     = (const float*)d_in[0];
    const float* mask  = (const float*)d_in[1];
    const int*   ei    = (const int*)d_in[2];
    const int*   batch = (const int*)d_in[3];
    const float* Wg    = (const float*)d_in[4];
    const float* attS  = (const float*)d_in[5];
    const float* attD  = (const float*)d_in[6];
    const float* bg    = (const float*)d_in[7];
    const float* Wl    = (const float*)d_in[8];
    const float* bl    = (const float*)d_in[9];
    float* out = (float*)d_out;

    int n = in_sizes[0] / 64;
    int E = in_sizes[2] / 2;
    int nb = (n + SCB - 1) / SCB;

    k_nodebits<<<(64 * n + 255) / 256, 256>>>(mask, n);
    k_edge1   <<<(E + 255) / 256, 256>>>(ei, E, n);
    k_scanA   <<<nb, 256>>>(n);
    k_scanB   <<<1, 64>>>(nb, n, batch);
    k_scanC   <<<nb, 256>>>(n);
    k_fill    <<<(E + 255) / 256, 256>>>(ei, E, n);
    k_gemm    <<<(n + 15) / 16, 256>>>(x, Wg, attS, attD, n);
    k_attn    <<<(n + 7) / 8, 256>>>(bg, n);
    k_final   <<<(n + 31) / 32, 256>>>(Wl, bl, batch, out, n);
}

// round 14
// speedup vs baseline: 1.4099x; 1.0598x over previous
#include <cuda_runtime.h>
#include <cuda_bf16.h>
#include <cuda_fp16.h>

// Problem constants (fixed by the dataset)
#define NMAX 50000
#define EMAX 800000
#define GMAXG 64
#define SCB 1024                 // elements per scan block
#define SCMAXB ((NMAX + SCB - 1) / SCB)

// ---------------- scratch (device globals; no allocation allowed) -------------
__device__ __align__(8) unsigned int g_mbits[2 * NMAX];     // result mask bits
__device__ __align__(8) unsigned int g_nodebits[2 * NMAX];  // mask[n,f]>0 bits
__device__ __align__(16) int g_cnt[NMAX];                   // zeroed by k_scan after use
__device__ __align__(16) int g_off[NMAX + 4];
__device__ __align__(16) int g_cursor[NMAX];
__device__ int g_agg[SCMAXB];
__device__ int g_flag[SCMAXB];                              // zeroed by k_mid after use
__device__ int g_csr[EMAX];                    // src ids grouped by dst
__device__ __align__(16) __half g_xwh[(size_t)NMAX * 256];  // fp16 features
__device__ __align__(16) __half g_gath[(size_t)NMAX * 256]; // fp16 (gat+b)*mask
__device__ __align__(16) float g_as[NMAX * 4];
__device__ __align__(16) float g_ad[NMAX * 4];
__device__ int g_deg[GMAXG];

__device__ __forceinline__ float lrelu(float a) { return fmaxf(a, 0.2f * a); }
__device__ __forceinline__ float2 h2f(unsigned int u) {
    __half2 h = *reinterpret_cast<const __half2*>(&u);
    return __half22float2(h);
}
// packed fp32x2 FMA: d = a*b + d  (PTX ISA 8.6, sm_100+)
__device__ __forceinline__ void fma2(unsigned long long& d,
                                     unsigned long long a,
                                     unsigned long long b) {
    asm("fma.rn.f32x2 %0, %1, %2, %0;" : "+l"(d) : "l"(a), "l"(b));
}
__device__ __forceinline__ float2 unpk(unsigned long long p) {
    float x, y;
    asm("mov.b64 {%0, %1}, %2;" : "=f"(x), "=f"(y) : "l"(p));
    return make_float2(x, y);
}

// ---------------- K1: nodebits role || edge-count role ------------------------
// blocks [0, blocksA): per-warp nodebits + zero mbits (+ block 0 zeroes g_deg)
// blocks [blocksA, ...): per-edge in-degree count into g_cnt
__global__ void k_pre(const float* __restrict__ mask, const int* __restrict__ ei,
                      int E, int n, int blocksA) {
    int b = blockIdx.x, tid = threadIdx.x;
    if (b < blocksA) {
        if (b == 0 && tid < GMAXG) g_deg[tid] = 0;
        int gw = b * 8 + (tid >> 5);
        int lane = tid & 31;
        int node = gw >> 1, half = gw & 1;
        if (node >= n) return;
        float v = mask[node * 64 + half * 32 + lane];
        unsigned int bb = __ballot_sync(0xffffffffu, v > 0.f);
        if (lane == 0) {
            g_nodebits[node * 2 + half] = bb;
            g_mbits[node * 2 + half] = 0u;
        }
    } else {
        int e = (b - blocksA) * 256 + tid;
        if (e >= E) return;
        int c = ei[E + e];   // edge_index[1] = dst
        if ((unsigned)c < (unsigned)n) atomicAdd(&g_cnt[c], 1);
    }
}

// ---------------- single-kernel decoupled-lookback exclusive scan -------------
// 49 blocks (all co-resident -> deadlock-free). Aggregate-only lookback.
// Also: folds the batch_idx histogram (graph sizes) and zeroes g_cnt after use.
__device__ __forceinline__ void scan_load4(int base, int n,
                                           int& v0, int& v1, int& v2, int& v3) {
    v0 = v1 = v2 = v3 = 0;
    if (base + 3 < n) {
        int4 c = *(const int4*)(g_cnt + base);
        v0 = c.x; v1 = c.y; v2 = c.z; v3 = c.w;
    } else {
        if (base + 0 < n) v0 = g_cnt[base + 0];
        if (base + 1 < n) v1 = g_cnt[base + 1];
        if (base + 2 < n) v2 = g_cnt[base + 2];
        if (base + 3 < n) v3 = g_cnt[base + 3];
    }
}

__global__ void k_scan(const int* __restrict__ batch, int n, int nb) {
    __shared__ int ts[256];
    __shared__ int hist[GMAXG];
    __shared__ int preds[64];
    __shared__ int sbase;
    int tid = threadIdx.x, b = blockIdx.x;
    int base = b * SCB + tid * 4;
    int v0, v1, v2, v3;
    scan_load4(base, n, v0, v1, v2, v3);
    int s = v0 + v1 + v2 + v3;
    ts[tid] = s;
    if (tid < GMAXG) hist[tid] = 0;
    __syncthreads();
#pragma unroll
    for (int d = 1; d < 256; d <<= 1) {
        int t = (tid >= d) ? ts[tid - d] : 0;
        __syncthreads();
        ts[tid] += t;
        __syncthreads();
    }
    // publish this block's aggregate
    if (tid == 0) {
        g_agg[b] = ts[255];
        __threadfence();
        atomicExch(&g_flag[b], 1);
    }
    // batch histogram for this block's node range (overlaps lookback wait)
    int hi = min((b + 1) * SCB, n);
    for (int i = b * SCB + tid; i < hi; i += 256) atomicAdd(&hist[batch[i]], 1);
    // lookback: thread t < b waits for predecessor t's aggregate
    int pred = 0;
    if (tid < b) {
        while (atomicAdd(&g_flag[tid], 0) == 0) {}
        pred = atomicAdd(&g_agg[tid], 0);
    }
    if (tid < 64) preds[tid] = pred;
    __syncthreads();
    if (tid == 0) {
        int e = 0;
        for (int i = 0; i < 64; i++) e += preds[i];
        sbase = e;
    }
    __syncthreads();

    int excl = sbase + ts[tid] - s;
    int o0 = excl, o1 = o0 + v0, o2 = o1 + v1, o3 = o2 + v2;
    if (base + 3 < n) {
        *(int4*)(g_off + base)    = make_int4(o0, o1, o2, o3);
        *(int4*)(g_cursor + base) = make_int4(o0, o1, o2, o3);
        *(int4*)(g_cnt + base)    = make_int4(0, 0, 0, 0);   // reset for next replay
    } else {
        if (base + 0 < n) { g_off[base + 0] = o0; g_cursor[base + 0] = o0; g_cnt[base + 0] = 0; }
        if (base + 1 < n) { g_off[base + 1] = o1; g_cursor[base + 1] = o1; g_cnt[base + 1] = 0; }
        if (base + 2 < n) { g_off[base + 2] = o2; g_cursor[base + 2] = o2; g_cnt[base + 2] = 0; }
        if (base + 3 < n) { g_off[base + 3] = o3; g_cursor[base + 3] = o3; g_cnt[base + 3] = 0; }
    }
    if (b == nb - 1 && tid == 255) g_off[n] = sbase + ts[255];
    if (tid < GMAXG && hist[tid]) atomicAdd(&g_deg[tid], hist[tid]);
}

// ---------------- K2: gemm role || CSR-fill role ------------------------------
// gemm: FMA-bound. fill: L2-atomic-bound. Merged so they overlap on-chip.
__global__ void k_mid(const float* __restrict__ x, const float* __restrict__ Wg,
                      const float* __restrict__ attS, const float* __restrict__ attD,
                      const int* __restrict__ ei, int E, int n, int gemmBlocks) {
    __shared__ float xs[16 * 68];
    __shared__ float partS[16][8];
    __shared__ float partD[16][8];
    int tid = threadIdx.x;

    if (blockIdx.x >= gemmBlocks) {
        // ---- fill role ----
        int fb = blockIdx.x - gemmBlocks;
        if (fb == 0 && tid < SCMAXB) g_flag[tid] = 0;   // reset scan flags for next replay
        int e = fb * 256 + tid;
        if (e >= E) return;
        int s = ei[e];           // edge_index[0] = src (mask target)
        int d = ei[E + e];       // edge_index[1] = dst (mask source)
        if ((unsigned)s >= (unsigned)n || (unsigned)d >= (unsigned)n) return;
        unsigned long long nb = ((const unsigned long long*)g_nodebits)[d];
        atomicOr((unsigned long long*)g_mbits + s, nb);
        int pos = atomicAdd(&g_cursor[d], 1);
        g_csr[pos] = s;
        return;
    }

    // ---- gemm role: xw = x @ W_gat^T (+ attention scalars) ----
    int row0 = blockIdx.x * 16;

    for (int idx = tid; idx < 16 * 64; idx += 256) {
        int r = idx >> 6, f = idx & 63;
        int row = row0 + r;
        xs[r * 68 + f] = (row < n) ? x[row * 64 + f] : 0.f;
    }
    __syncthreads();

    unsigned long long accp[16];
#pragma unroll
    for (int r = 0; r < 16; r++) accp[r] = 0ull;

    const ulonglong2* wrow = (const ulonglong2*)(Wg + tid * 64);
#pragma unroll
    for (int fc = 0; fc < 16; fc++) {
        ulonglong2 w = wrow[fc];
#pragma unroll
        for (int r = 0; r < 16; r++) {
            ulonglong2 xv = *(const ulonglong2*)(xs + r * 68 + fc * 4);
            fma2(accp[r], w.x, xv.x);
            fma2(accp[r], w.y, xv.y);
        }
    }

    float acc[16];
#pragma unroll
    for (int r = 0; r < 16; r++) {
        float2 u = unpk(accp[r]);
        acc[r] = u.x + u.y;
    }

#pragma unroll
    for (int r = 0; r < 16; r++) {
        int row = row0 + r;
        if (row < n) g_xwh[(size_t)row * 256 + tid] = __float2half(acc[r]);
    }

    float aS = attS[tid], aD = attD[tid];
    int wid = tid >> 5, lane = tid & 31;
#pragma unroll
    for (int r = 0; r < 16; r++) {
        float sS = acc[r] * aS, sD = acc[r] * aD;
#pragma unroll
        for (int o = 16; o; o >>= 1) {
            sS += __shfl_xor_sync(0xffffffffu, sS, o);
            sD += __shfl_xor_sync(0xffffffffu, sD, o);
        }
        if (lane == 0) { partS[r][wid] = sS; partD[r][wid] = sD; }
    }
    __syncthreads();
    if (tid < 128) {
        int r = tid >> 3, h = (tid >> 1) & 3, sd = tid & 1;
        int row = row0 + r;
        if (row < n) {
            if (sd == 0) g_as[row * 4 + h] = partS[r][2 * h] + partS[r][2 * h + 1];
            else         g_ad[row * 4 + h] = partD[r][2 * h] + partD[r][2 * h + 1];
        }
    }
}

// ---------------- attention: warp per destination node -----------------------
// Lane owns channels 8*lane..8*lane+7 (head = lane>>3); one LDG.128 per edge.
// Epilogue applies bias + mask and stores fp16.
__global__ void k_attn(const float* __restrict__ bg, int n) {
    __shared__ int ssrc[8][32];
    __shared__ float4 sp[8][32];
    int w = threadIdx.x >> 5, lane = threadIdx.x & 31;
    int i = blockIdx.x * 8 + w;
    if (i >= n) return;

    int off0 = g_off[i];
    int len = g_off[i + 1] - off0;

    const float4* as4 = (const float4*)g_as;
    float4 ad = ((const float4*)g_ad)[i];
    float4 asl = as4[i];

    float self0 = __expf(lrelu(asl.x + ad.x));
    float self1 = __expf(lrelu(asl.y + ad.y));
    float self2 = __expf(lrelu(asl.z + ad.z));
    float self3 = __expf(lrelu(asl.w + ad.w));
    float den0 = (lane == 0) ? self0 : 0.f;
    float den1 = (lane == 0) ? self1 : 0.f;
    float den2 = (lane == 0) ? self2 : 0.f;
    float den3 = (lane == 0) ? self3 : 0.f;

    int h = lane >> 3;   // head owned by this lane's channels
    float selfh = (h == 0) ? self0 : (h == 1) ? self1 : (h == 2) ? self2 : self3;

    const uint4* xwh = (const uint4*)g_xwh;   // 32 x uint4 (8 halves) per node
    float a0, a1, a2, a3, a4, a5, a6, a7;
    {
        uint4 v = xwh[(size_t)i * 32 + lane];
        float2 f0 = h2f(v.x), f1 = h2f(v.y), f2 = h2f(v.z), f3 = h2f(v.w);
        a0 = selfh * f0.x; a1 = selfh * f0.y;
        a2 = selfh * f1.x; a3 = selfh * f1.y;
        a4 = selfh * f2.x; a5 = selfh * f2.y;
        a6 = selfh * f3.x; a7 = selfh * f3.y;
    }

    for (int base = 0; base < len; base += 32) {
        int k = base + lane;
        if (k < len) {
            int s = g_csr[off0 + k];
            float4 a = as4[s];
            float p0 = __expf(lrelu(a.x + ad.x));
            float p1 = __expf(lrelu(a.y + ad.y));
            float p2 = __expf(lrelu(a.z + ad.z));
            float p3 = __expf(lrelu(a.w + ad.w));
            den0 += p0; den1 += p1; den2 += p2; den3 += p3;
            ssrc[w][lane] = s;
            sp[w][lane] = make_float4(p0, p1, p2, p3);
        }
        __syncwarp();
        int cnt = min(32, len - base);
#pragma unroll 4
        for (int t = 0; t < cnt; t++) {
            int s = ssrc[w][t];
            float p = ((const float*)&sp[w][t])[h];
            uint4 v = xwh[(size_t)s * 32 + lane];
            float2 f0 = h2f(v.x), f1 = h2f(v.y), f2 = h2f(v.z), f3 = h2f(v.w);
            a0 = fmaf(p, f0.x, a0); a1 = fmaf(p, f0.y, a1);
            a2 = fmaf(p, f1.x, a2); a3 = fmaf(p, f1.y, a3);
            a4 = fmaf(p, f2.x, a4); a5 = fmaf(p, f2.y, a5);
            a6 = fmaf(p, f3.x, a6); a7 = fmaf(p, f3.y, a7);
        }
        __syncwarp();
    }

#pragma unroll
    for (int o = 16; o; o >>= 1) {
        den0 += __shfl_xor_sync(0xffffffffu, den0, o);
        den1 += __shfl_xor_sync(0xffffffffu, den1, o);
        den2 += __shfl_xor_sync(0xffffffffu, den2, o);
        den3 += __shfl_xor_sync(0xffffffffu, den3, o);
    }
    float inv0 = 1.f / (den0 + 1e-16f);
    float inv1 = 1.f / (den1 + 1e-16f);
    float inv2 = 1.f / (den2 + 1e-16f);
    float inv3 = 1.f / (den3 + 1e-16f);
    float invh = (h == 0) ? inv0 : (h == 1) ? inv1 : (h == 2) ? inv2 : inv3;

    // epilogue: (acc*inv + bias) * maskbit, store fp16
    const float4* bg4 = (const float4*)(bg + lane * 8);
    float4 b0 = bg4[0], b1 = bg4[1];
    unsigned long long mb = ((const unsigned long long*)g_mbits)[i];
    int bbase = 8 * (lane & 7);
    float r0 = (a0 * invh + b0.x) * (float)((mb >> (bbase + 0)) & 1);
    float r1 = (a1 * invh + b0.y) * (float)((mb >> (bbase + 1)) & 1);
    float r2 = (a2 * invh + b0.z) * (float)((mb >> (bbase + 2)) & 1);
    float r3 = (a3 * invh + b0.w) * (float)((mb >> (bbase + 3)) & 1);
    float r4 = (a4 * invh + b1.x) * (float)((mb >> (bbase + 4)) & 1);
    float r5 = (a5 * invh + b1.y) * (float)((mb >> (bbase + 5)) & 1);
    float r6 = (a6 * invh + b1.z) * (float)((mb >> (bbase + 6)) & 1);
    float r7 = (a7 * invh + b1.w) * (float)((mb >> (bbase + 7)) & 1);

    uint4 o;
    __half2 h0 = __floats2half2_rn(r0, r1);
    __half2 h1 = __floats2half2_rn(r2, r3);
    __half2 h2 = __floats2half2_rn(r4, r5);
    __half2 h3 = __floats2half2_rn(r6, r7);
    o.x = *(unsigned int*)&h0;
    o.y = *(unsigned int*)&h1;
    o.z = *(unsigned int*)&h2;
    o.w = *(unsigned int*)&h3;
    ((uint4*)g_gath)[(size_t)i * 32 + lane] = o;
}

// ---------------- final: out = gath @ W_lin^T + b_lin, graph-size norm -------
__global__ void k_final(const float* __restrict__ Wl,
                        const float* __restrict__ bl,
                        const int* __restrict__ batch,
                        float* __restrict__ out, int n) {
    __shared__ float grow[32 * 260];
    int tid = threadIdx.x;
    int row0 = blockIdx.x * 32;

    const uint4* gh = (const uint4*)g_gath;
    for (int idx = tid; idx < 32 * 32; idx += 256) {
        int r = idx >> 5, u = idx & 31;
        int row = row0 + r;
        uint4 v = make_uint4(0u, 0u, 0u, 0u);
        if (row < n) v = gh[(size_t)row * 32 + u];
        float* dst = grow + r * 260 + u * 8;
        *(float2*)(dst + 0) = h2f(v.x);
        *(float2*)(dst + 2) = h2f(v.y);
        *(float2*)(dst + 4) = h2f(v.z);
        *(float2*)(dst + 6) = h2f(v.w);
    }
    __syncthreads();

    int d2 = tid & 63, rg = tid >> 6;
    unsigned long long accp[8];
#pragma unroll
    for (int k = 0; k < 8; k++) accp[k] = 0ull;

    const ulonglong2* wl2 = (const ulonglong2*)(Wl + d2 * 256);
#pragma unroll 4
    for (int c4 = 0; c4 < 64; c4++) {
        ulonglong2 wv = wl2[c4];
#pragma unroll
        for (int k = 0; k < 8; k++) {
            ulonglong2 g = *(const ulonglong2*)(grow + (rg * 8 + k) * 260 + c4 * 4);
            fma2(accp[k], wv.x, g.x);
            fma2(accp[k], wv.y, g.y);
        }
    }

    float b = bl[d2];
#pragma unroll
    for (int k = 0; k < 8; k++) {
        int row = row0 + rg * 8 + k;
        if (row < n) {
            float2 u = unpk(accp[k]);
            float acc = u.x + u.y;
            int bi = batch[row];
            int dd = (bi >= 0 && bi < GMAXG) ? g_deg[bi] : 0;
            float dv = (dd > 0) ? (float)dd : 1.f;
            out[row * 64 + d2] = (acc + b) * rsqrtf(dv);
        }
    }
}

// ---------------- launcher ----------------------------------------------------
extern "C" void kernel_launch(void* const* d_in, const int* in_sizes, int n_in,
                              void* d_out, int out_size) {
    const float* x     = (const float*)d_in[0];
    const float* mask  = (const float*)d_in[1];
    const int*   ei    = (const int*)d_in[2];
    const int*   batch = (const int*)d_in[3];
    const float* Wg    = (const float*)d_in[4];
    const float* attS  = (const float*)d_in[5];
    const float* attD  = (const float*)d_in[6];
    const float* bg    = (const float*)d_in[7];
    const float* Wl    = (const float*)d_in[8];
    const float* bl    = (const float*)d_in[9];
    float* out = (float*)d_out;

    int n = in_sizes[0] / 64;
    int E = in_sizes[2] / 2;
    int blocksA = (64 * n + 255) / 256;
    int blocksE = (E + 255) / 256;
    int gemmB   = (n + 15) / 16;
    int nb      = (n + SCB - 1) / SCB;

    k_pre  <<<blocksA + blocksE, 256>>>(mask, ei, E, n, blocksA);
    k_scan <<<nb, 256>>>(batch, n, nb);
    k_mid  <<<gemmB + blocksE, 256>>>(x, Wg, attS, attD, ei, E, n, gemmB);
    k_attn <<<(n + 7) / 8, 256>>>(bg, n);
    k_final<<<(n + 31) / 32, 256>>>(Wl, bl, batch, out, n);
}